// round 1
// baseline (speedup 1.0000x reference)
#include <cuda_runtime.h>
#include <math.h>

// Problem constants
#define B_      64
#define NFEAT   196
#define ENC_Hc  2048
#define DEC_Hc  1024
#define ATTN_c  512
#define EMB_c   512
#define VOCAB_c 32000
#define TSTEPS  31          // T-1
#define XDIM    (ENC_Hc + DEC_Hc)   // 3072
#define GDIM    (4 * DEC_Hc)        // 4096
#define SPLITK_GATES 4

// ---------------- scratch (device globals; no allocation allowed) -----------
__device__ float g_Uf[(size_t)B_ * NFEAT * ATTN_c];          // 25.7 MB
__device__ float g_featmean[B_ * ENC_Hc];
__device__ float g_h[B_ * DEC_Hc];
__device__ float g_c[B_ * DEC_Hc];
__device__ float g_alpha[B_ * NFEAT];
__device__ float g_X[B_ * XDIM];                              // [context | h]
__device__ float g_GatesPart[SPLITK_GATES * B_ * GDIM];       // split-K partials
__device__ float g_EmbAll[(size_t)TSTEPS * B_ * EMB_c];       // [t][b][emb]
__device__ float g_Gemb[(size_t)TSTEPS * B_ * GDIM];          // emb@Wih[:512]+b_ih
__device__ float g_Hall[(size_t)B_ * TSTEPS * DEC_Hc];        // [b][t][dec]
__device__ float g_Wcat[(size_t)XDIM * GDIM];                 // [Wih[512:]; Whh]

// ---------------- generic fp32 SGEMM: C = A@B (+bias)(+Cin) -----------------
// A: [M,K] with row stride lda. B: [K,N] row-major. Tiles 64x64, BK=16.
// blockIdx.x = M-tile, blockIdx.y = N-tile (so concurrent blocks share B in L2),
// blockIdx.z = K split (partials written to C + z*M*N, no bias/Cin when z-split).
__global__ void sgemm64(const float* __restrict__ A, int lda,
                        const float* __restrict__ Bm, int N, int K,
                        const float* __restrict__ Cin,
                        const float* __restrict__ bias,
                        float* __restrict__ C, int M)
{
    __shared__ float As[16][64];
    __shared__ float Bs[16][64];
    const int tid = threadIdx.x;
    const int bm = blockIdx.x, bn = blockIdx.y, bz = blockIdx.z;
    const int kChunk = K / gridDim.z;
    const int k0 = bz * kChunk;
    const float* Ab = A + (size_t)bm * 64 * lda + k0;
    const float* Bb = Bm + (size_t)k0 * N + bn * 64;

    float acc[4][4];
#pragma unroll
    for (int i = 0; i < 4; i++)
#pragma unroll
        for (int j = 0; j < 4; j++) acc[i][j] = 0.f;

    const int aRow = tid >> 2, aK = (tid & 3) << 2;   // A tile: 64 rows x 16 k
    const int bRow = tid >> 4, bC = (tid & 15) << 2;  // B tile: 16 k x 64 cols
    const int ty = tid >> 4, tx = tid & 15;

    for (int kt = 0; kt < kChunk; kt += 16) {
        float4 av = *(const float4*)(Ab + (size_t)aRow * lda + kt + aK);
        As[aK + 0][aRow] = av.x; As[aK + 1][aRow] = av.y;
        As[aK + 2][aRow] = av.z; As[aK + 3][aRow] = av.w;
        *(float4*)&Bs[bRow][bC] =
            *(const float4*)(Bb + (size_t)(kt + bRow) * N + bC);
        __syncthreads();
#pragma unroll
        for (int k = 0; k < 16; k++) {
            float4 a = *(const float4*)&As[k][ty << 2];
            float4 b = *(const float4*)&Bs[k][tx << 2];
            acc[0][0] += a.x * b.x; acc[0][1] += a.x * b.y;
            acc[0][2] += a.x * b.z; acc[0][3] += a.x * b.w;
            acc[1][0] += a.y * b.x; acc[1][1] += a.y * b.y;
            acc[1][2] += a.y * b.z; acc[1][3] += a.y * b.w;
            acc[2][0] += a.z * b.x; acc[2][1] += a.z * b.y;
            acc[2][2] += a.z * b.z; acc[2][3] += a.z * b.w;
            acc[3][0] += a.w * b.x; acc[3][1] += a.w * b.y;
            acc[3][2] += a.w * b.z; acc[3][3] += a.w * b.w;
        }
        __syncthreads();
    }

    float* Cb = C + (size_t)bz * M * N;
    const int r0 = bm * 64 + (ty << 2), c0 = bn * 64 + (tx << 2);
#pragma unroll
    for (int i = 0; i < 4; i++) {
#pragma unroll
        for (int j = 0; j < 4; j++) {
            float v = acc[i][j];
            const int r = r0 + i, c = c0 + j;
            if (bias) v += bias[c];
            if (Cin)  v += Cin[(size_t)r * N + c];
            Cb[(size_t)r * N + c] = v;
        }
    }
}

// ---------------- feature mean over N_FEAT --------------------------------
__global__ void feat_mean_kernel(const float* __restrict__ f,
                                 float* __restrict__ out)
{
    const int b = blockIdx.x;
    for (int k = threadIdx.x; k < ENC_Hc; k += blockDim.x) {
        float s = 0.f;
        for (int n = 0; n < NFEAT; n++)
            s += f[((size_t)b * NFEAT + n) * ENC_Hc + k];
        out[b * ENC_Hc + k] = s * (1.0f / (float)NFEAT);
    }
}

// ---------------- embedding gather: EmbAll[t*64+b][:] = table[cap[b][t]] ----
__global__ void emb_gather_kernel(const int* __restrict__ captions,
                                  const float* __restrict__ table,
                                  float* __restrict__ embAll)
{
    const int m = blockIdx.x;        // t*64 + b
    const int t = m >> 6, b = m & 63;
    const int cap = captions[b * 32 + t];
    const float4* src = (const float4*)(table + (size_t)cap * EMB_c);
    float4* dst = (float4*)(embAll + (size_t)m * EMB_c);
    for (int i = threadIdx.x; i < EMB_c / 4; i += blockDim.x) dst[i] = src[i];
}

// ---------------- build Wcat = [W_ih rows 512..2559 ; W_hh] ----------------
__global__ void wcat_kernel(const float* __restrict__ Wih,
                            const float* __restrict__ Whh,
                            float* __restrict__ Wcat)
{
    const size_t idx = (size_t)blockIdx.x * blockDim.x + threadIdx.x;
    const size_t e = idx * 4;
    if (e >= (size_t)XDIM * GDIM) return;
    const int r = (int)(e / GDIM), c = (int)(e % GDIM);
    const float* src = (r < ENC_Hc)
        ? (Wih + (size_t)(EMB_c + r) * GDIM + c)
        : (Whh + (size_t)(r - ENC_Hc) * GDIM + c);
    *(float4*)&Wcat[e] = *(const float4*)src;
}

// ---------------- attention scores + softmax (one block per batch) ---------
// Fuses hW = h@W_w + b_w, scores = W_a . tanh(Uf + hW), softmax -> alpha.
__global__ void attn_scores_kernel(const float* __restrict__ Uf,
                                   const float* __restrict__ h,
                                   const float* __restrict__ Ww,
                                   const float* __restrict__ bw,
                                   const float* __restrict__ Wa,
                                   float* __restrict__ alpha,
                                   float* __restrict__ outAttn)  // +t*196, or null
{
    const int b = blockIdx.x;
    const int tid = threadIdx.x;     // 256 threads
    __shared__ float sh[DEC_Hc];
    __shared__ float shw[ATTN_c];
    __shared__ float swa[ATTN_c];
    __shared__ float ssc[256];
    __shared__ float red[256];

    for (int j = tid; j < DEC_Hc; j += 256) sh[j] = h[b * DEC_Hc + j];
    for (int k = tid; k < ATTN_c; k += 256) swa[k] = Wa[k];
    __syncthreads();

    // hW[k] for k = tid and tid+256
    {
        float s0 = bw[tid], s1 = bw[tid + 256];
#pragma unroll 8
        for (int j = 0; j < DEC_Hc; j++) {
            const float hv = sh[j];
            s0 += hv * Ww[(size_t)j * ATTN_c + tid];
            s1 += hv * Ww[(size_t)j * ATTN_c + tid + 256];
        }
        shw[tid] = s0; shw[tid + 256] = s1;
    }
    __syncthreads();

    // scores: warp per feature index
    const int warp = tid >> 5, lane = tid & 31;
    for (int n = warp; n < NFEAT; n += 8) {
        const float* uf = Uf + ((size_t)b * NFEAT + n) * ATTN_c;
        float s = 0.f;
#pragma unroll 4
        for (int k = lane; k < ATTN_c; k += 32)
            s += tanhf(uf[k] + shw[k]) * swa[k];
#pragma unroll
        for (int o = 16; o; o >>= 1) s += __shfl_xor_sync(0xffffffffu, s, o);
        if (lane == 0) ssc[n] = s;
    }
    __syncthreads();

    // softmax over 196
    float v = (tid < NFEAT) ? ssc[tid] : -INFINITY;
    red[tid] = v; __syncthreads();
    for (int o = 128; o; o >>= 1) {
        if (tid < o) red[tid] = fmaxf(red[tid], red[tid + o]);
        __syncthreads();
    }
    const float mx = red[0]; __syncthreads();
    const float e = (tid < NFEAT) ? expf(v - mx) : 0.f;
    red[tid] = e; __syncthreads();
    for (int o = 128; o; o >>= 1) {
        if (tid < o) red[tid] += red[tid + o];
        __syncthreads();
    }
    const float inv = 1.f / red[0];
    if (tid < NFEAT) {
        const float a = e * inv;
        alpha[b * NFEAT + tid] = a;
        if (outAttn) outAttn[(size_t)b * TSTEPS * NFEAT + tid] = a;
    }
}

// ---------------- context = alpha @ features; also X = [context | h] -------
__global__ void context_kernel(const float* __restrict__ feat,
                               const float* __restrict__ alpha,
                               const float* __restrict__ h,
                               float* __restrict__ X)
{
    const int b = blockIdx.x, y = blockIdx.y, tid = threadIdx.x;
    if (y == 8) {   // copy h into X tail
        for (int j = tid; j < DEC_Hc; j += 256)
            X[b * XDIM + ENC_Hc + j] = h[b * DEC_Hc + j];
        return;
    }
    __shared__ float sa[NFEAT];
    for (int n = tid; n < NFEAT; n += 256) sa[n] = alpha[b * NFEAT + n];
    __syncthreads();
    const int j = y * 256 + tid;
    float s = 0.f;
#pragma unroll 4
    for (int n = 0; n < NFEAT; n++)
        s += sa[n] * feat[((size_t)b * NFEAT + n) * ENC_Hc + j];
    X[b * XDIM + j] = s;
}

// ---------------- LSTM pointwise: reduce split-K partials + gates ----------
__global__ void lstm_kernel(const float* __restrict__ P,       // [4][64][4096]
                            const float* __restrict__ GembT,   // [64][4096]
                            const float* __restrict__ bhh,
                            float* __restrict__ h,
                            float* __restrict__ c,
                            float* __restrict__ Hall, int t)
{
    const int b = blockIdx.x, tid = threadIdx.x;
    const size_t ps = (size_t)B_ * GDIM;
    for (int j = tid; j < DEC_Hc; j += 256) {
        float g[4];
#pragma unroll
        for (int q = 0; q < 4; q++) {
            const int col = q * DEC_Hc + j;
            float s = GembT[(size_t)b * GDIM + col] + bhh[col];
            s += P[0 * ps + (size_t)b * GDIM + col];
            s += P[1 * ps + (size_t)b * GDIM + col];
            s += P[2 * ps + (size_t)b * GDIM + col];
            s += P[3 * ps + (size_t)b * GDIM + col];
            g[q] = s;
        }
        const float ig = 1.f / (1.f + expf(-g[0]));
        const float fg = 1.f / (1.f + expf(-g[1]));
        const float gg = tanhf(g[2]);
        const float og = 1.f / (1.f + expf(-g[3]));
        const float cn = fg * c[b * DEC_Hc + j] + ig * gg;
        const float hn = og * tanhf(cn);
        c[b * DEC_Hc + j] = cn;
        h[b * DEC_Hc + j] = hn;
        Hall[((size_t)b * TSTEPS + t) * DEC_Hc + j] = hn;
    }
}

// ---------------------------------------------------------------------------
extern "C" void kernel_launch(void* const* d_in, const int* in_sizes, int n_in,
                              void* d_out, int out_size)
{
    const float* features = (const float*)d_in[0];
    const int*   captions = (const int*)d_in[1];
    const float* emb_tab  = (const float*)d_in[2];
    const float* W_u  = (const float*)d_in[3];
    const float* b_u  = (const float*)d_in[4];
    const float* W_w  = (const float*)d_in[5];
    const float* b_w  = (const float*)d_in[6];
    const float* W_a  = (const float*)d_in[7];
    // d_in[8] = b_a: constant shift, softmax-invariant and zero -> unused
    const float* W_ih = (const float*)d_in[9];
    const float* b_ih = (const float*)d_in[10];
    const float* W_hh = (const float*)d_in[11];
    const float* b_hh = (const float*)d_in[12];
    const float* W_fc = (const float*)d_in[13];
    const float* b_fc = (const float*)d_in[14];
    const float* W_h0 = (const float*)d_in[15];
    const float* b_h0 = (const float*)d_in[16];
    const float* W_c0 = (const float*)d_in[17];
    const float* b_c0 = (const float*)d_in[18];

    float* outPred = (float*)d_out;
    const size_t predElems = (size_t)B_ * TSTEPS * VOCAB_c;   // 63,488,000
    const size_t attnElems = (size_t)B_ * TSTEPS * NFEAT;     // 388,864
    float* outAttn =
        ((size_t)out_size >= predElems + attnElems) ? outPred + predElems : nullptr;

    // symbol addresses (deterministic, capture-safe)
    float *pUf, *pFM, *pH, *pC, *pAl, *pX, *pGP, *pEA, *pGE, *pHA, *pWC;
    cudaGetSymbolAddress((void**)&pUf, g_Uf);
    cudaGetSymbolAddress((void**)&pFM, g_featmean);
    cudaGetSymbolAddress((void**)&pH,  g_h);
    cudaGetSymbolAddress((void**)&pC,  g_c);
    cudaGetSymbolAddress((void**)&pAl, g_alpha);
    cudaGetSymbolAddress((void**)&pX,  g_X);
    cudaGetSymbolAddress((void**)&pGP, g_GatesPart);
    cudaGetSymbolAddress((void**)&pEA, g_EmbAll);
    cudaGetSymbolAddress((void**)&pGE, g_Gemb);
    cudaGetSymbolAddress((void**)&pHA, g_Hall);
    cudaGetSymbolAddress((void**)&pWC, g_Wcat);

    // ---- one-time (per call) prologue ----
    feat_mean_kernel<<<B_, 256>>>(features, pFM);

    // h0 = featmean @ W_h0 + b_h0 ; c0 likewise
    sgemm64<<<dim3(1, DEC_Hc / 64, 1), 256>>>(pFM, ENC_Hc, W_h0, DEC_Hc, ENC_Hc,
                                              nullptr, b_h0, pH, B_);
    sgemm64<<<dim3(1, DEC_Hc / 64, 1), 256>>>(pFM, ENC_Hc, W_c0, DEC_Hc, ENC_Hc,
                                              nullptr, b_c0, pC, B_);

    // Uf = features @ W_u + b_u   [12544, 512]
    sgemm64<<<dim3(B_ * NFEAT / 64, ATTN_c / 64, 1), 256>>>(
        features, ENC_Hc, W_u, ATTN_c, ENC_Hc, nullptr, b_u, pUf, B_ * NFEAT);

    // gather embeddings and precompute Gemb = emb @ W_ih[:512] + b_ih
    emb_gather_kernel<<<TSTEPS * B_, 128>>>(captions, emb_tab, pEA);
    sgemm64<<<dim3(TSTEPS * B_ / 64, GDIM / 64, 1), 256>>>(
        pEA, EMB_c, W_ih, GDIM, EMB_c, nullptr, b_ih, pGE, TSTEPS * B_);

    // Wcat = [W_ih rows 512..2559 ; W_hh]
    wcat_kernel<<<(XDIM * GDIM / 4 + 255) / 256, 256>>>(W_ih, W_hh, pWC);

    // ---- recurrence ----
    for (int t = 0; t < TSTEPS; t++) {
        attn_scores_kernel<<<B_, 256>>>(pUf, pH, W_w, b_w, W_a, pAl,
                                        outAttn ? outAttn + (size_t)t * NFEAT
                                                : nullptr);
        context_kernel<<<dim3(B_, 9), 256>>>(features, pAl, pH, pX);

        // gates partials: [64,3072] @ Wcat[3072,4096], split-K = 4
        sgemm64<<<dim3(1, GDIM / 64, SPLITK_GATES), 256>>>(
            pX, XDIM, pWC, GDIM, XDIM, nullptr, nullptr, pGP, B_);

        lstm_kernel<<<B_, 256>>>(pGP, pGE + (size_t)t * B_ * GDIM, b_hh,
                                 pH, pC, pHA, t);
    }

    // ---- logits: H_all[1984,1024] @ W_fc[1024,32000] + b_fc -> preds ----
    sgemm64<<<dim3(B_ * TSTEPS / 64, VOCAB_c / 64, 1), 256>>>(
        pHA, DEC_Hc, W_fc, VOCAB_c, DEC_Hc, nullptr, b_fc, outPred, B_ * TSTEPS);
}

// round 2
// speedup vs baseline: 1.2048x; 1.2048x over previous
#include <cuda_runtime.h>
#include <math.h>

// Problem constants
#define B_      64
#define NFEAT   196
#define ENC_Hc  2048
#define DEC_Hc  1024
#define ATTN_c  512
#define EMB_c   512
#define VOCAB_c 32000
#define TSTEPS  31          // T-1
#define XDIM    (ENC_Hc + DEC_Hc)   // 3072
#define GDIM    (4 * DEC_Hc)        // 4096
#define SPLITK_GATES 8

// ---------------- scratch (device globals; no allocation allowed) -----------
__device__ float g_Uf[(size_t)B_ * NFEAT * ATTN_c];          // 25.7 MB
__device__ float g_featmean[B_ * ENC_Hc];
__device__ float g_h[B_ * DEC_Hc];
__device__ float g_c[B_ * DEC_Hc];
__device__ float g_X[B_ * XDIM];                              // [context | h]
__device__ float g_GatesPart[SPLITK_GATES * B_ * GDIM];       // split-K partials
__device__ float g_EmbAll[(size_t)TSTEPS * B_ * EMB_c];       // [t*64+b][emb]
__device__ float g_Gemb[(size_t)TSTEPS * B_ * GDIM];          // emb@Wih[:512]+b_ih
__device__ float g_Hall[(size_t)B_ * TSTEPS * DEC_Hc];        // [b][t][dec]
__device__ float g_Wcat[(size_t)XDIM * GDIM];                 // [Wih[512:]; Whh]

// =============== 128x128x16 double-buffered SGEMM, 8x8 microtile ============
// C[M,N] = A[M,K] @ B[K,N] (+bias). lda = row stride of A. N % 128 == 0,
// K % 16 == 0. M handled with clamp/guard (tail tiles OK).
__global__ __launch_bounds__(256, 2)
void sgemm128(const float* __restrict__ A, int lda,
              const float* __restrict__ Bm, int N, int K,
              const float* __restrict__ bias,
              float* __restrict__ C, int M)
{
    __shared__ float As[2][16][132];   // k-major, padded (132*4B % 16B == 0)
    __shared__ float Bs[2][16][128];

    const int tid = threadIdx.x;
    const int bm = blockIdx.x, bn = blockIdx.y;

    // global-load assignments
    const int aRow = tid >> 1;              // 0..127
    const int aK   = (tid & 1) * 8;         // 0 or 8
    const int bRow = tid >> 4;              // 0..15
    const int bCol = (tid & 15) * 4;        // 0..60

    const int rowBase = bm * 128;
    const int aRowG = min(rowBase + aRow, M - 1);   // clamp for tail tiles
    const float* Ap = A + (size_t)aRowG * lda + aK;
    const float* Bp = Bm + (size_t)bRow * N + (size_t)bn * 128 + bCol;

    const int ty = tid >> 4, tx = tid & 15;

    float acc[8][8];
#pragma unroll
    for (int i = 0; i < 8; i++)
#pragma unroll
        for (int j = 0; j < 8; j++) acc[i][j] = 0.f;

    const int nTiles = K / 16;
    float4 pa0, pa1, pb0, pb1;

    // preload tile 0
    pa0 = *(const float4*)(Ap);
    pa1 = *(const float4*)(Ap + 4);
    pb0 = *(const float4*)(Bp);
    pb1 = *(const float4*)(Bp + 64);
    As[0][aK + 0][aRow] = pa0.x; As[0][aK + 1][aRow] = pa0.y;
    As[0][aK + 2][aRow] = pa0.z; As[0][aK + 3][aRow] = pa0.w;
    As[0][aK + 4][aRow] = pa1.x; As[0][aK + 5][aRow] = pa1.y;
    As[0][aK + 6][aRow] = pa1.z; As[0][aK + 7][aRow] = pa1.w;
    *(float4*)&Bs[0][bRow][bCol]      = pb0;
    *(float4*)&Bs[0][bRow][bCol + 64] = pb1;
    __syncthreads();

    for (int t = 0; t < nTiles; t++) {
        const int cur = t & 1, nxt = cur ^ 1;
        if (t + 1 < nTiles) {
            const float* Ap2 = Ap + (t + 1) * 16;
            const float* Bp2 = Bp + (size_t)(t + 1) * 16 * N;
            pa0 = *(const float4*)(Ap2);
            pa1 = *(const float4*)(Ap2 + 4);
            pb0 = *(const float4*)(Bp2);
            pb1 = *(const float4*)(Bp2 + 64);
        }
#pragma unroll
        for (int k = 0; k < 16; k++) {
            float a[8], b[8];
            *(float4*)&a[0] = *(const float4*)&As[cur][k][ty * 8];
            *(float4*)&a[4] = *(const float4*)&As[cur][k][ty * 8 + 4];
            *(float4*)&b[0] = *(const float4*)&Bs[cur][k][tx * 8];
            *(float4*)&b[4] = *(const float4*)&Bs[cur][k][tx * 8 + 4];
#pragma unroll
            for (int i = 0; i < 8; i++)
#pragma unroll
                for (int j = 0; j < 8; j++) acc[i][j] += a[i] * b[j];
        }
        if (t + 1 < nTiles) {
            As[nxt][aK + 0][aRow] = pa0.x; As[nxt][aK + 1][aRow] = pa0.y;
            As[nxt][aK + 2][aRow] = pa0.z; As[nxt][aK + 3][aRow] = pa0.w;
            As[nxt][aK + 4][aRow] = pa1.x; As[nxt][aK + 5][aRow] = pa1.y;
            As[nxt][aK + 6][aRow] = pa1.z; As[nxt][aK + 7][aRow] = pa1.w;
            *(float4*)&Bs[nxt][bRow][bCol]      = pb0;
            *(float4*)&Bs[nxt][bRow][bCol + 64] = pb1;
            __syncthreads();
        }
    }

    // epilogue
    const int r0 = rowBase + ty * 8;
    const int c0 = bn * 128 + tx * 8;
    float bb[8];
#pragma unroll
    for (int j = 0; j < 8; j++) bb[j] = bias ? bias[c0 + j] : 0.f;
#pragma unroll
    for (int i = 0; i < 8; i++) {
        const int r = r0 + i;
        if (r < M) {
            float4 v0, v1;
            v0.x = acc[i][0] + bb[0]; v0.y = acc[i][1] + bb[1];
            v0.z = acc[i][2] + bb[2]; v0.w = acc[i][3] + bb[3];
            v1.x = acc[i][4] + bb[4]; v1.y = acc[i][5] + bb[5];
            v1.z = acc[i][6] + bb[6]; v1.w = acc[i][7] + bb[7];
            *(float4*)&C[(size_t)r * N + c0]     = v0;
            *(float4*)&C[(size_t)r * N + c0 + 4] = v1;
        }
    }
}

// =============== skinny gates GEMM: [64,3072] @ Wcat[3072,4096] =============
// 64x128 tile, 4x8 microtile, split-K = 8 -> partials P[z][64][4096].
__global__ __launch_bounds__(256)
void sgemm_gates(const float* __restrict__ A,   // X [64, XDIM]
                 const float* __restrict__ Bm,  // Wcat [XDIM, GDIM]
                 float* __restrict__ P)
{
    __shared__ float As[16][68];
    __shared__ float Bs[16][128];

    const int tid = threadIdx.x;
    const int bn = blockIdx.x;             // 0..31
    const int bz = blockIdx.y;             // 0..7
    const int kChunk = XDIM / SPLITK_GATES;   // 384
    const int k0 = bz * kChunk;

    const int aRow = tid >> 2, aK = (tid & 3) * 4;     // 64 rows x 16 k
    const int bRow = tid >> 4, bCol = (tid & 15) * 4;  // 16 k x 128 cols
    const float* Ap = A + (size_t)aRow * XDIM + k0 + aK;
    const float* Bp = Bm + (size_t)(k0 + bRow) * GDIM + bn * 128 + bCol;

    const int ty = tid >> 4, tx = tid & 15;

    float acc[4][8];
#pragma unroll
    for (int i = 0; i < 4; i++)
#pragma unroll
        for (int j = 0; j < 8; j++) acc[i][j] = 0.f;

    const int nTiles = kChunk / 16;   // 24
    for (int t = 0; t < nTiles; t++) {
        float4 av  = *(const float4*)(Ap + t * 16);
        float4 bv0 = *(const float4*)(Bp + (size_t)t * 16 * GDIM);
        float4 bv1 = *(const float4*)(Bp + (size_t)t * 16 * GDIM + 64);
        __syncthreads();
        As[aK + 0][aRow] = av.x; As[aK + 1][aRow] = av.y;
        As[aK + 2][aRow] = av.z; As[aK + 3][aRow] = av.w;
        *(float4*)&Bs[bRow][bCol]      = bv0;
        *(float4*)&Bs[bRow][bCol + 64] = bv1;
        __syncthreads();
#pragma unroll
        for (int k = 0; k < 16; k++) {
            float a[4], b[8];
            *(float4*)&a[0] = *(const float4*)&As[k][ty * 4];
            *(float4*)&b[0] = *(const float4*)&Bs[k][tx * 8];
            *(float4*)&b[4] = *(const float4*)&Bs[k][tx * 8 + 4];
#pragma unroll
            for (int i = 0; i < 4; i++)
#pragma unroll
                for (int j = 0; j < 8; j++) acc[i][j] += a[i] * b[j];
        }
    }

    float* Cb = P + (size_t)bz * B_ * GDIM;
    const int c0 = bn * 128 + tx * 8;
#pragma unroll
    for (int i = 0; i < 4; i++) {
        const int r = ty * 4 + i;
        float4 v0, v1;
        v0.x = acc[i][0]; v0.y = acc[i][1]; v0.z = acc[i][2]; v0.w = acc[i][3];
        v1.x = acc[i][4]; v1.y = acc[i][5]; v1.z = acc[i][6]; v1.w = acc[i][7];
        *(float4*)&Cb[(size_t)r * GDIM + c0]     = v0;
        *(float4*)&Cb[(size_t)r * GDIM + c0 + 4] = v1;
    }
}

// ---------------- feature mean over N_FEAT --------------------------------
__global__ void feat_mean_kernel(const float* __restrict__ f,
                                 float* __restrict__ out)
{
    const int b = blockIdx.x;
    for (int k = threadIdx.x; k < ENC_Hc; k += blockDim.x) {
        float s = 0.f;
        for (int n = 0; n < NFEAT; n++)
            s += f[((size_t)b * NFEAT + n) * ENC_Hc + k];
        out[b * ENC_Hc + k] = s * (1.0f / (float)NFEAT);
    }
}

// ---------------- embedding gather -----------------------------------------
__global__ void emb_gather_kernel(const int* __restrict__ captions,
                                  const float* __restrict__ table,
                                  float* __restrict__ embAll)
{
    const int m = blockIdx.x;        // t*64 + b
    const int t = m >> 6, b = m & 63;
    const int cap = captions[b * 32 + t];
    const float4* src = (const float4*)(table + (size_t)cap * EMB_c);
    float4* dst = (float4*)(embAll + (size_t)m * EMB_c);
    for (int i = threadIdx.x; i < EMB_c / 4; i += blockDim.x) dst[i] = src[i];
}

// ---------------- build Wcat = [W_ih rows 512..2559 ; W_hh] ----------------
__global__ void wcat_kernel(const float* __restrict__ Wih,
                            const float* __restrict__ Whh,
                            float* __restrict__ Wcat)
{
    const size_t idx = (size_t)blockIdx.x * blockDim.x + threadIdx.x;
    const size_t e = idx * 4;
    if (e >= (size_t)XDIM * GDIM) return;
    const int r = (int)(e / GDIM), c = (int)(e % GDIM);
    const float* src = (r < ENC_Hc)
        ? (Wih + (size_t)(EMB_c + r) * GDIM + c)
        : (Whh + (size_t)(r - ENC_Hc) * GDIM + c);
    *(float4*)&Wcat[e] = *(const float4*)src;
}

// =============== fused attention: hW, scores, softmax, context, X ==========
// one block per batch element, 512 threads
__global__ __launch_bounds__(512)
void attn_ctx_kernel(const float* __restrict__ Uf,
                     const float* __restrict__ feat,
                     const float* __restrict__ h,
                     const float* __restrict__ Ww,
                     const float* __restrict__ bw,
                     const float* __restrict__ Wa,
                     float* __restrict__ X,
                     float* __restrict__ outAttn)  // already offset by t*NFEAT (or null)
{
    const int b = blockIdx.x;
    const int tid = threadIdx.x;

    __shared__ float sh[DEC_Hc];
    __shared__ float shw[ATTN_c];
    __shared__ float swa[ATTN_c];
    __shared__ float sa[256];
    __shared__ float red[512];

    for (int j = tid; j < DEC_Hc; j += 512) sh[j] = h[b * DEC_Hc + j];
    if (tid < ATTN_c) swa[tid] = Wa[tid];
    __syncthreads();

    // hW[tid] = h @ W_w[:, tid] + bw[tid], 4 partial chains for ILP
    if (tid < ATTN_c) {
        float s0 = bw[tid], s1 = 0.f, s2 = 0.f, s3 = 0.f;
#pragma unroll 4
        for (int j = 0; j < DEC_Hc; j += 4) {
            s0 += sh[j + 0] * Ww[(size_t)(j + 0) * ATTN_c + tid];
            s1 += sh[j + 1] * Ww[(size_t)(j + 1) * ATTN_c + tid];
            s2 += sh[j + 2] * Ww[(size_t)(j + 2) * ATTN_c + tid];
            s3 += sh[j + 3] * Ww[(size_t)(j + 3) * ATTN_c + tid];
        }
        shw[tid] = (s0 + s1) + (s2 + s3);
    }
    __syncthreads();

    // scores: one warp per feature row
    const int warp = tid >> 5, lane = tid & 31;
    for (int n = warp; n < NFEAT; n += 16) {
        const float* uf = Uf + ((size_t)b * NFEAT + n) * ATTN_c;
        float s = 0.f;
#pragma unroll 4
        for (int k = lane; k < ATTN_c; k += 32)
            s += tanhf(uf[k] + shw[k]) * swa[k];
#pragma unroll
        for (int o = 16; o; o >>= 1) s += __shfl_xor_sync(0xffffffffu, s, o);
        if (lane == 0) sa[n] = s;
    }
    __syncthreads();

    // softmax over NFEAT=196
    float v = (tid < NFEAT) ? sa[tid] : -INFINITY;
    red[tid] = v; __syncthreads();
    for (int o = 256; o; o >>= 1) {
        if (tid < o) red[tid] = fmaxf(red[tid], red[tid + o]);
        __syncthreads();
    }
    const float mx = red[0]; __syncthreads();
    const float e = (tid < NFEAT) ? expf(v - mx) : 0.f;
    red[tid] = e; __syncthreads();
    for (int o = 256; o; o >>= 1) {
        if (tid < o) red[tid] += red[tid + o];
        __syncthreads();
    }
    const float inv = 1.f / red[0];
    __syncthreads();
    if (tid < NFEAT) {
        const float a = e * inv;
        sa[tid] = a;
        if (outAttn) outAttn[(size_t)b * TSTEPS * NFEAT + tid] = a;
    }
    __syncthreads();

    // context: 4 contiguous cols per thread (float4), X = [context | h]
    float4 cacc = {0.f, 0.f, 0.f, 0.f};
    const float* fb = feat + (size_t)b * NFEAT * ENC_Hc + tid * 4;
#pragma unroll 4
    for (int n = 0; n < NFEAT; n++) {
        const float al = sa[n];
        const float4 fv = *(const float4*)(fb + (size_t)n * ENC_Hc);
        cacc.x += al * fv.x; cacc.y += al * fv.y;
        cacc.z += al * fv.z; cacc.w += al * fv.w;
    }
    *(float4*)&X[b * XDIM + tid * 4] = cacc;
    for (int j = tid; j < DEC_Hc; j += 512)
        X[b * XDIM + ENC_Hc + j] = sh[j];
}

// ---------------- LSTM pointwise: reduce split-K partials + gates ----------
__global__ void lstm_kernel(const float* __restrict__ P,       // [8][64][4096]
                            const float* __restrict__ GembT,   // [64][4096]
                            const float* __restrict__ bhh,
                            float* __restrict__ h,
                            float* __restrict__ c,
                            float* __restrict__ Hall, int t)
{
    const int b = blockIdx.x, tid = threadIdx.x;
    const size_t ps = (size_t)B_ * GDIM;
    for (int j = tid; j < DEC_Hc; j += 256) {
        float g[4];
#pragma unroll
        for (int q = 0; q < 4; q++) {
            const int col = q * DEC_Hc + j;
            float s = GembT[(size_t)b * GDIM + col] + bhh[col];
#pragma unroll
            for (int z = 0; z < SPLITK_GATES; z++)
                s += P[z * ps + (size_t)b * GDIM + col];
            g[q] = s;
        }
        const float ig = 1.f / (1.f + expf(-g[0]));
        const float fg = 1.f / (1.f + expf(-g[1]));
        const float gg = tanhf(g[2]);
        const float og = 1.f / (1.f + expf(-g[3]));
        const float cn = fg * c[b * DEC_Hc + j] + ig * gg;
        const float hn = og * tanhf(cn);
        c[b * DEC_Hc + j] = cn;
        h[b * DEC_Hc + j] = hn;
        Hall[((size_t)b * TSTEPS + t) * DEC_Hc + j] = hn;
    }
}

// ---------------------------------------------------------------------------
extern "C" void kernel_launch(void* const* d_in, const int* in_sizes, int n_in,
                              void* d_out, int out_size)
{
    const float* features = (const float*)d_in[0];
    const int*   captions = (const int*)d_in[1];
    const float* emb_tab  = (const float*)d_in[2];
    const float* W_u  = (const float*)d_in[3];
    const float* b_u  = (const float*)d_in[4];
    const float* W_w  = (const float*)d_in[5];
    const float* b_w  = (const float*)d_in[6];
    const float* W_a  = (const float*)d_in[7];
    // d_in[8] = b_a (zero, softmax-invariant)
    const float* W_ih = (const float*)d_in[9];
    const float* b_ih = (const float*)d_in[10];
    const float* W_hh = (const float*)d_in[11];
    const float* b_hh = (const float*)d_in[12];
    const float* W_fc = (const float*)d_in[13];
    const float* b_fc = (const float*)d_in[14];
    const float* W_h0 = (const float*)d_in[15];
    const float* b_h0 = (const float*)d_in[16];
    const float* W_c0 = (const float*)d_in[17];
    const float* b_c0 = (const float*)d_in[18];

    float* outPred = (float*)d_out;
    const size_t predElems = (size_t)B_ * TSTEPS * VOCAB_c;
    const size_t attnElems = (size_t)B_ * TSTEPS * NFEAT;
    float* outAttn =
        ((size_t)out_size >= predElems + attnElems) ? outPred + predElems : nullptr;

    float *pUf, *pFM, *pH, *pC, *pX, *pGP, *pEA, *pGE, *pHA, *pWC;
    cudaGetSymbolAddress((void**)&pUf, g_Uf);
    cudaGetSymbolAddress((void**)&pFM, g_featmean);
    cudaGetSymbolAddress((void**)&pH,  g_h);
    cudaGetSymbolAddress((void**)&pC,  g_c);
    cudaGetSymbolAddress((void**)&pX,  g_X);
    cudaGetSymbolAddress((void**)&pGP, g_GatesPart);
    cudaGetSymbolAddress((void**)&pEA, g_EmbAll);
    cudaGetSymbolAddress((void**)&pGE, g_Gemb);
    cudaGetSymbolAddress((void**)&pHA, g_Hall);
    cudaGetSymbolAddress((void**)&pWC, g_Wcat);

    // ---- prologue ----
    feat_mean_kernel<<<B_, 256>>>(features, pFM);

    // h0/c0: [64,2048]@[2048,1024]
    sgemm128<<<dim3(1, DEC_Hc / 128), 256>>>(pFM, ENC_Hc, W_h0, DEC_Hc, ENC_Hc,
                                             b_h0, pH, B_);
    sgemm128<<<dim3(1, DEC_Hc / 128), 256>>>(pFM, ENC_Hc, W_c0, DEC_Hc, ENC_Hc,
                                             b_c0, pC, B_);

    // Uf = features @ W_u + b_u   [12544, 512]
    sgemm128<<<dim3(B_ * NFEAT / 128, ATTN_c / 128), 256>>>(
        features, ENC_Hc, W_u, ATTN_c, ENC_Hc, b_u, pUf, B_ * NFEAT);

    // embeddings + Gemb = emb @ W_ih[:512] + b_ih   [1984, 4096]
    emb_gather_kernel<<<TSTEPS * B_, 128>>>(captions, emb_tab, pEA);
    sgemm128<<<dim3((TSTEPS * B_ + 127) / 128, GDIM / 128), 256>>>(
        pEA, EMB_c, W_ih, GDIM, EMB_c, b_ih, pGE, TSTEPS * B_);

    // Wcat
    wcat_kernel<<<((size_t)XDIM * GDIM / 4 + 255) / 256, 256>>>(W_ih, W_hh, pWC);

    // ---- recurrence ----
    for (int t = 0; t < TSTEPS; t++) {
        attn_ctx_kernel<<<B_, 512>>>(pUf, features, pH, W_w, b_w, W_a, pX,
                                     outAttn ? outAttn + (size_t)t * NFEAT
                                             : nullptr);
        sgemm_gates<<<dim3(GDIM / 128, SPLITK_GATES), 256>>>(pX, pWC, pGP);
        lstm_kernel<<<B_, 256>>>(pGP, pGE + (size_t)t * B_ * GDIM, b_hh,
                                 pH, pC, pHA, t);
    }

    // ---- logits: [1984,1024] @ [1024,32000] + b_fc ----
    sgemm128<<<dim3((B_ * TSTEPS + 127) / 128, VOCAB_c / 128), 256>>>(
        pHA, DEC_Hc, W_fc, VOCAB_c, DEC_Hc, b_fc, outPred, B_ * TSTEPS);
}

// round 4
// speedup vs baseline: 1.3664x; 1.1341x over previous
#include <cuda_runtime.h>
#include <cuda_bf16.h>
#include <math.h>
#include <stdint.h>

// Problem constants
#define B_      64
#define NFEAT   196
#define ENC_Hc  2048
#define DEC_Hc  1024
#define ATTN_c  512
#define EMB_c   512
#define VOCAB_c 32000
#define TSTEPS  31
#define XDIM    (ENC_Hc + DEC_Hc)   // 3072
#define GDIM    (4 * DEC_Hc)        // 4096
#define SPLITK_GATES 8

// ---------------- scratch (device globals; no allocation allowed) -----------
__device__ float g_Uf[(size_t)B_ * NFEAT * ATTN_c];
__device__ float g_featmean[B_ * ENC_Hc];
__device__ float g_h[B_ * DEC_Hc];
__device__ float g_c[B_ * DEC_Hc];
__device__ float g_alpha[B_ * NFEAT];
__device__ float g_X[B_ * XDIM];
__device__ float g_GatesPart[SPLITK_GATES * B_ * GDIM];
__device__ float g_EmbAll[(size_t)TSTEPS * B_ * EMB_c];
__device__ float g_Gemb[(size_t)TSTEPS * B_ * GDIM];
__device__ float g_Hall[(size_t)B_ * TSTEPS * DEC_Hc];
// pre-split weights: [N][K/2] entries of {hi bf16x2, lo bf16x2}
__device__ uint2 g_WuSp[(size_t)ATTN_c * (ENC_Hc / 2)];       // 4 MB
__device__ uint2 g_WihSp[(size_t)GDIM * (EMB_c / 2)];         // 8 MB
__device__ uint2 g_WfcSp[(size_t)VOCAB_c * (DEC_Hc / 2)];     // 131 MB
__device__ uint2 g_WcatSp[(size_t)GDIM * (XDIM / 2)];         // 48 MB

// ---------------- bf16 pack helpers -----------------------------------------
__device__ __forceinline__ uint32_t pack_bf2(__nv_bfloat16 a, __nv_bfloat16 b) {
    union { __nv_bfloat162 v; uint32_t u; } cv;
    cv.v.x = a; cv.v.y = b;            // .x = low half = even k
    return cv.u;
}
__device__ __forceinline__ uint2 split_pack(float x0, float x1) {
    __nv_bfloat16 h0 = __float2bfloat16(x0);
    __nv_bfloat16 h1 = __float2bfloat16(x1);
    float l0 = x0 - __bfloat162float(h0);
    float l1 = x1 - __bfloat162float(h1);
    uint2 e;
    e.x = pack_bf2(h0, h1);
    e.y = pack_bf2(__float2bfloat16(l0), __float2bfloat16(l1));
    return e;
}
// smem entry index with swizzle (16 kp per row, 8B entries)
__device__ __forceinline__ int eidx(int row, int kp) {
    return row * 16 + ((kp + ((row & 3) << 2)) & 15);
}
__device__ __forceinline__ void mma_bf16(float* c, uint32_t a0, uint32_t a1,
                                         uint32_t a2, uint32_t a3,
                                         uint32_t b0, uint32_t b1) {
    asm volatile(
        "mma.sync.aligned.m16n8k16.row.col.f32.bf16.bf16.f32 "
        "{%0,%1,%2,%3}, {%4,%5,%6,%7}, {%8,%9}, {%0,%1,%2,%3};"
        : "+f"(c[0]), "+f"(c[1]), "+f"(c[2]), "+f"(c[3])
        : "r"(a0), "r"(a1), "r"(a2), "r"(a3), "r"(b0), "r"(b1));
}

// =============== bf16x3 tensor GEMM: C = A @ Bsp^T (+bias) ==================
// A [M,K] fp32 row-major (lda), split in-kernel. Bsp [N][kpTot] uint2 pre-split.
// Block tile 128x128, k chunk 32. grid (Mtiles, N/128, splits).
// With splits>1: k0 = z*kLen, C += z*M*N, bias should be null.
__global__ __launch_bounds__(256)
void tgemm_bf16(const float* __restrict__ A, int lda,
                const uint2* __restrict__ Bsp, int kpTot,
                const float* __restrict__ bias,
                float* __restrict__ C, int M, int N, int kLen)
{
    extern __shared__ uint2 sm[];
    // layout: A0 [0,2048) B0 [2048,4096) A1 [4096,6144) B1 [6144,8192)
    uint2* bufA[2] = { sm,        sm + 4096 };
    uint2* bufB[2] = { sm + 2048, sm + 6144 };

    const int tid = threadIdx.x;
    const int lane = tid & 31, wid = tid >> 5;
    const int warp_mi = wid >> 1;          // 0..3  (m band of 32)
    const int warp_ni = wid & 1;           // 0..1  (n band of 64)
    const int rowBase = blockIdx.x * 128;
    const int colBase = blockIdx.y * 128;
    const int k0 = blockIdx.z * kLen;
    C += (size_t)blockIdx.z * M * N;

    // staging assignment: thread -> (row 0..127, 8 consecutive kp)
    const int sRow = tid >> 1;
    const int sKp8 = (tid & 1) * 8;
    const int aRowG = min(rowBase + sRow, M - 1);
    const float* Aptr = A + (size_t)aRowG * lda + k0;
    const uint2* Bptr = Bsp + (size_t)(colBase + sRow) * kpTot + (k0 >> 1);

    float acc[2][8][4];
#pragma unroll
    for (int mt = 0; mt < 2; mt++)
#pragma unroll
        for (int nt = 0; nt < 8; nt++)
#pragma unroll
            for (int q = 0; q < 4; q++) acc[mt][nt][q] = 0.f;

    const int nCh = kLen / 32;
    float2 rA[8];
    uint2  rB[8];

    // preload chunk 0
#pragma unroll
    for (int i = 0; i < 8; i++) {
        rA[i] = *(const float2*)(Aptr + (sKp8 + i) * 2);
        rB[i] = Bptr[sKp8 + i];
    }
#pragma unroll
    for (int i = 0; i < 8; i++) {
        bufA[0][eidx(sRow, sKp8 + i)] = split_pack(rA[i].x, rA[i].y);
        bufB[0][eidx(sRow, sKp8 + i)] = rB[i];
    }
    __syncthreads();

    for (int ch = 0; ch < nCh; ch++) {
        const int cur = ch & 1;
        if (ch + 1 < nCh) {
            const float* Ap2 = Aptr + (ch + 1) * 32;
            const uint2* Bp2 = Bptr + (ch + 1) * 16;
#pragma unroll
            for (int i = 0; i < 8; i++) {
                rA[i] = *(const float2*)(Ap2 + (sKp8 + i) * 2);
                rB[i] = Bp2[sKp8 + i];
            }
        }
        // mma over this chunk (k = 32 -> two k16 steps)
#pragma unroll
        for (int k16 = 0; k16 < 2; k16++) {
            const int ak = k16 * 8 + (lane & 3);
            const int arl = warp_mi * 32 + (lane >> 2);
            uint2 af[2][4];
#pragma unroll
            for (int mt = 0; mt < 2; mt++) {
                const int r0 = arl + mt * 16;
                af[mt][0] = bufA[cur][eidx(r0,     ak)];
                af[mt][1] = bufA[cur][eidx(r0 + 8, ak)];
                af[mt][2] = bufA[cur][eidx(r0,     ak + 4)];
                af[mt][3] = bufA[cur][eidx(r0 + 8, ak + 4)];
            }
#pragma unroll
            for (int nt = 0; nt < 8; nt++) {
                const int nb = warp_ni * 64 + nt * 8 + (lane >> 2);
                const uint2 b0 = bufB[cur][eidx(nb, ak)];
                const uint2 b1 = bufB[cur][eidx(nb, ak + 4)];
#pragma unroll
                for (int mt = 0; mt < 2; mt++) {
                    // hi*hi
                    mma_bf16(acc[mt][nt], af[mt][0].x, af[mt][1].x,
                             af[mt][2].x, af[mt][3].x, b0.x, b1.x);
                    // hi*lo
                    mma_bf16(acc[mt][nt], af[mt][0].x, af[mt][1].x,
                             af[mt][2].x, af[mt][3].x, b0.y, b1.y);
                    // lo*hi
                    mma_bf16(acc[mt][nt], af[mt][0].y, af[mt][1].y,
                             af[mt][2].y, af[mt][3].y, b0.x, b1.x);
                }
            }
        }
        if (ch + 1 < nCh) {
            const int nxt = cur ^ 1;
#pragma unroll
            for (int i = 0; i < 8; i++) {
                bufA[nxt][eidx(sRow, sKp8 + i)] = split_pack(rA[i].x, rA[i].y);
                bufB[nxt][eidx(sRow, sKp8 + i)] = rB[i];
            }
            __syncthreads();
        }
    }

    // epilogue
#pragma unroll
    for (int mt = 0; mt < 2; mt++) {
#pragma unroll
        for (int nt = 0; nt < 8; nt++) {
            const int r0 = rowBase + warp_mi * 32 + mt * 16 + (lane >> 2);
            const int cc = colBase + warp_ni * 64 + nt * 8 + (lane & 3) * 2;
            float bv0 = 0.f, bv1 = 0.f;
            if (bias) { bv0 = bias[cc]; bv1 = bias[cc + 1]; }
            if (r0 < M) {
                float2 v = { acc[mt][nt][0] + bv0, acc[mt][nt][1] + bv1 };
                *(float2*)&C[(size_t)r0 * N + cc] = v;
            }
            if (r0 + 8 < M) {
                float2 v = { acc[mt][nt][2] + bv0, acc[mt][nt][3] + bv1 };
                *(float2*)&C[(size_t)(r0 + 8) * N + cc] = v;
            }
        }
    }
}

// =========== transpose + bf16 hi/lo split: in[K][N] -> out[N][kp] ===========
// grid (N/32, Kpart/64), block (32,8). kpOff/kpTot in kp units (2 k per kp).
__global__ void ts_split(const float* __restrict__ in, int N,
                         uint2* __restrict__ out, int kpOff, int kpTot)
{
    __shared__ float t[64][33];
    const int n0 = blockIdx.x * 32, k0 = blockIdx.y * 64;
    const int tx = threadIdx.x, ty = threadIdx.y;
    for (int i = ty; i < 64; i += 8)
        t[i][tx] = in[(size_t)(k0 + i) * N + n0 + tx];
    __syncthreads();
    for (int i = ty; i < 32; i += 8) {
        out[(size_t)(n0 + tx) * kpTot + kpOff + (k0 >> 1) + i] =
            split_pack(t[2 * i][tx], t[2 * i + 1][tx]);
    }
}

// =============== fp32 fallback SGEMM (h0/c0 only, tiny) =====================
__global__ __launch_bounds__(256, 2)
void sgemm128(const float* __restrict__ A, int lda,
              const float* __restrict__ Bm, int N, int K,
              const float* __restrict__ bias,
              float* __restrict__ C, int M)
{
    __shared__ float As[2][16][132];
    __shared__ float Bs[2][16][128];
    const int tid = threadIdx.x;
    const int bm = blockIdx.x, bn = blockIdx.y;
    const int aRow = tid >> 1, aK = (tid & 1) * 8;
    const int bRow = tid >> 4, bCol = (tid & 15) * 4;
    const int rowBase = bm * 128;
    const int aRowG = min(rowBase + aRow, M - 1);
    const float* Ap = A + (size_t)aRowG * lda + aK;
    const float* Bp = Bm + (size_t)bRow * N + (size_t)bn * 128 + bCol;
    const int ty = tid >> 4, tx = tid & 15;
    float acc[8][8];
#pragma unroll
    for (int i = 0; i < 8; i++)
#pragma unroll
        for (int j = 0; j < 8; j++) acc[i][j] = 0.f;
    const int nTiles = K / 16;
    float4 pa0, pa1, pb0, pb1;
    pa0 = *(const float4*)(Ap); pa1 = *(const float4*)(Ap + 4);
    pb0 = *(const float4*)(Bp); pb1 = *(const float4*)(Bp + 64);
    As[0][aK+0][aRow]=pa0.x; As[0][aK+1][aRow]=pa0.y;
    As[0][aK+2][aRow]=pa0.z; As[0][aK+3][aRow]=pa0.w;
    As[0][aK+4][aRow]=pa1.x; As[0][aK+5][aRow]=pa1.y;
    As[0][aK+6][aRow]=pa1.z; As[0][aK+7][aRow]=pa1.w;
    *(float4*)&Bs[0][bRow][bCol]      = pb0;
    *(float4*)&Bs[0][bRow][bCol + 64] = pb1;
    __syncthreads();
    for (int t = 0; t < nTiles; t++) {
        const int cur = t & 1, nxt = cur ^ 1;
        if (t + 1 < nTiles) {
            const float* Ap2 = Ap + (t + 1) * 16;
            const float* Bp2 = Bp + (size_t)(t + 1) * 16 * N;
            pa0 = *(const float4*)(Ap2); pa1 = *(const float4*)(Ap2 + 4);
            pb0 = *(const float4*)(Bp2); pb1 = *(const float4*)(Bp2 + 64);
        }
#pragma unroll
        for (int k = 0; k < 16; k++) {
            float a[8], b[8];
            *(float4*)&a[0] = *(const float4*)&As[cur][k][ty * 8];
            *(float4*)&a[4] = *(const float4*)&As[cur][k][ty * 8 + 4];
            *(float4*)&b[0] = *(const float4*)&Bs[cur][k][tx * 8];
            *(float4*)&b[4] = *(const float4*)&Bs[cur][k][tx * 8 + 4];
#pragma unroll
            for (int i = 0; i < 8; i++)
#pragma unroll
                for (int j = 0; j < 8; j++) acc[i][j] += a[i] * b[j];
        }
        if (t + 1 < nTiles) {
            As[nxt][aK+0][aRow]=pa0.x; As[nxt][aK+1][aRow]=pa0.y;
            As[nxt][aK+2][aRow]=pa0.z; As[nxt][aK+3][aRow]=pa0.w;
            As[nxt][aK+4][aRow]=pa1.x; As[nxt][aK+5][aRow]=pa1.y;
            As[nxt][aK+6][aRow]=pa1.z; As[nxt][aK+7][aRow]=pa1.w;
            *(float4*)&Bs[nxt][bRow][bCol]      = pb0;
            *(float4*)&Bs[nxt][bRow][bCol + 64] = pb1;
            __syncthreads();
        }
    }
    const int r0 = rowBase + ty * 8;
    const int c0 = bn * 128 + tx * 8;
#pragma unroll
    for (int i = 0; i < 8; i++) {
        const int r = r0 + i;
        if (r < M) {
#pragma unroll
            for (int j = 0; j < 8; j++)
                C[(size_t)r * N + c0 + j] = acc[i][j] + bias[c0 + j];
        }
    }
}

// ---------------- misc small kernels ----------------------------------------
__global__ void feat_mean_kernel(const float* __restrict__ f,
                                 float* __restrict__ out)
{
    const int b = blockIdx.x;
    for (int k = threadIdx.x; k < ENC_Hc; k += blockDim.x) {
        float s = 0.f;
        for (int n = 0; n < NFEAT; n++)
            s += f[((size_t)b * NFEAT + n) * ENC_Hc + k];
        out[b * ENC_Hc + k] = s * (1.0f / (float)NFEAT);
    }
}

__global__ void emb_gather_kernel(const int* __restrict__ captions,
                                  const float* __restrict__ table,
                                  float* __restrict__ embAll)
{
    const int m = blockIdx.x;
    const int t = m >> 6, b = m & 63;
    const int cap = captions[b * 32 + t];
    const float4* src = (const float4*)(table + (size_t)cap * EMB_c);
    float4* dst = (float4*)(embAll + (size_t)m * EMB_c);
    for (int i = threadIdx.x; i < EMB_c / 4; i += blockDim.x) dst[i] = src[i];
}

// =============== attention scores + softmax -> alpha ========================
__global__ __launch_bounds__(512)
void attn_scores_kernel(const float* __restrict__ Uf,
                        const float* __restrict__ h,
                        const float* __restrict__ Ww,
                        const float* __restrict__ bw,
                        const float* __restrict__ Wa,
                        float* __restrict__ alpha,
                        float* __restrict__ outAttn)
{
    const int b = blockIdx.x;
    const int tid = threadIdx.x;
    __shared__ float sh[DEC_Hc];
    __shared__ float shw[ATTN_c];
    __shared__ float swa[ATTN_c];
    __shared__ float sa[256];
    __shared__ float red[512];

    for (int j = tid; j < DEC_Hc; j += 512) sh[j] = h[b * DEC_Hc + j];
    if (tid < ATTN_c) swa[tid] = Wa[tid];
    __syncthreads();
    if (tid < ATTN_c) {
        float s0 = bw[tid], s1 = 0.f, s2 = 0.f, s3 = 0.f;
#pragma unroll 4
        for (int j = 0; j < DEC_Hc; j += 4) {
            s0 += sh[j + 0] * Ww[(size_t)(j + 0) * ATTN_c + tid];
            s1 += sh[j + 1] * Ww[(size_t)(j + 1) * ATTN_c + tid];
            s2 += sh[j + 2] * Ww[(size_t)(j + 2) * ATTN_c + tid];
            s3 += sh[j + 3] * Ww[(size_t)(j + 3) * ATTN_c + tid];
        }
        shw[tid] = (s0 + s1) + (s2 + s3);
    }
    __syncthreads();
    const int warp = tid >> 5, lane = tid & 31;
    for (int n = warp; n < NFEAT; n += 16) {
        const float* uf = Uf + ((size_t)b * NFEAT + n) * ATTN_c;
        float s = 0.f;
#pragma unroll 4
        for (int k = lane; k < ATTN_c; k += 32)
            s += tanhf(uf[k] + shw[k]) * swa[k];
#pragma unroll
        for (int o = 16; o; o >>= 1) s += __shfl_xor_sync(0xffffffffu, s, o);
        if (lane == 0) sa[n] = s;
    }
    __syncthreads();
    float v = (tid < NFEAT) ? sa[tid] : -INFINITY;
    red[tid] = v; __syncthreads();
    for (int o = 256; o; o >>= 1) {
        if (tid < o) red[tid] = fmaxf(red[tid], red[tid + o]);
        __syncthreads();
    }
    const float mx = red[0]; __syncthreads();
    const float e = (tid < NFEAT) ? expf(v - mx) : 0.f;
    red[tid] = e; __syncthreads();
    for (int o = 256; o; o >>= 1) {
        if (tid < o) red[tid] += red[tid + o];
        __syncthreads();
    }
    const float inv = 1.f / red[0];
    if (tid < NFEAT) {
        const float a = e * inv;
        alpha[b * NFEAT + tid] = a;
        if (outAttn) outAttn[(size_t)b * TSTEPS * NFEAT + tid] = a;
    }
}

// =============== context = alpha @ features; X = [context | h] ==============
__global__ void context_kernel(const float* __restrict__ feat,
                               const float* __restrict__ alpha,
                               const float* __restrict__ h,
                               float* __restrict__ X)
{
    const int b = blockIdx.x, y = blockIdx.y, tid = threadIdx.x;
    if (y == 8) {
        for (int j = tid; j < DEC_Hc; j += 256)
            X[b * XDIM + ENC_Hc + j] = h[b * DEC_Hc + j];
        return;
    }
    __shared__ float sa[NFEAT];
    for (int n = tid; n < NFEAT; n += 256) sa[n] = alpha[b * NFEAT + n];
    __syncthreads();
    const int j = y * 256 + tid;
    float s = 0.f;
#pragma unroll 4
    for (int n = 0; n < NFEAT; n++)
        s += sa[n] * feat[((size_t)b * NFEAT + n) * ENC_Hc + j];
    X[b * XDIM + j] = s;
}

// =============== LSTM pointwise =============================================
__global__ void lstm_kernel(const float* __restrict__ P,
                            const float* __restrict__ GembT,
                            const float* __restrict__ bhh,
                            float* __restrict__ h,
                            float* __restrict__ c,
                            float* __restrict__ Hall, int t)
{
    const int b = blockIdx.x;
    const int j = blockIdx.y * 256 + threadIdx.x;
    const size_t ps = (size_t)B_ * GDIM;
    float g[4];
#pragma unroll
    for (int q = 0; q < 4; q++) {
        const int col = q * DEC_Hc + j;
        float s = GembT[(size_t)b * GDIM + col] + bhh[col];
#pragma unroll
        for (int z = 0; z < SPLITK_GATES; z++)
            s += P[z * ps + (size_t)b * GDIM + col];
        g[q] = s;
    }
    const float ig = 1.f / (1.f + expf(-g[0]));
    const float fg = 1.f / (1.f + expf(-g[1]));
    const float gg = tanhf(g[2]);
    const float og = 1.f / (1.f + expf(-g[3]));
    const float cn = fg * c[b * DEC_Hc + j] + ig * gg;
    const float hn = og * tanhf(cn);
    c[b * DEC_Hc + j] = cn;
    h[b * DEC_Hc + j] = hn;
    Hall[((size_t)b * TSTEPS + t) * DEC_Hc + j] = hn;
}

// ---------------------------------------------------------------------------
extern "C" void kernel_launch(void* const* d_in, const int* in_sizes, int n_in,
                              void* d_out, int out_size)
{
    const float* features = (const float*)d_in[0];
    const int*   captions = (const int*)d_in[1];
    const float* emb_tab  = (const float*)d_in[2];
    const float* W_u  = (const float*)d_in[3];
    const float* b_u  = (const float*)d_in[4];
    const float* W_w  = (const float*)d_in[5];
    const float* b_w  = (const float*)d_in[6];
    const float* W_a  = (const float*)d_in[7];
    const float* W_ih = (const float*)d_in[9];
    const float* b_ih = (const float*)d_in[10];
    const float* W_hh = (const float*)d_in[11];
    const float* b_hh = (const float*)d_in[12];
    const float* W_fc = (const float*)d_in[13];
    const float* b_fc = (const float*)d_in[14];
    const float* W_h0 = (const float*)d_in[15];
    const float* b_h0 = (const float*)d_in[16];
    const float* W_c0 = (const float*)d_in[17];
    const float* b_c0 = (const float*)d_in[18];

    float* outPred = (float*)d_out;
    const size_t predElems = (size_t)B_ * TSTEPS * VOCAB_c;
    const size_t attnElems = (size_t)B_ * TSTEPS * NFEAT;
    float* outAttn =
        ((size_t)out_size >= predElems + attnElems) ? outPred + predElems : nullptr;

    float *pUf, *pFM, *pH, *pC, *pAl, *pX, *pGP, *pEA, *pGE, *pHA;
    uint2 *pWuSp, *pWihSp, *pWfcSp, *pWcatSp;
    cudaGetSymbolAddress((void**)&pUf, g_Uf);
    cudaGetSymbolAddress((void**)&pFM, g_featmean);
    cudaGetSymbolAddress((void**)&pH,  g_h);
    cudaGetSymbolAddress((void**)&pC,  g_c);
    cudaGetSymbolAddress((void**)&pAl, g_alpha);
    cudaGetSymbolAddress((void**)&pX,  g_X);
    cudaGetSymbolAddress((void**)&pGP, g_GatesPart);
    cudaGetSymbolAddress((void**)&pEA, g_EmbAll);
    cudaGetSymbolAddress((void**)&pGE, g_Gemb);
    cudaGetSymbolAddress((void**)&pHA, g_Hall);
    cudaGetSymbolAddress((void**)&pWuSp,  g_WuSp);
    cudaGetSymbolAddress((void**)&pWihSp, g_WihSp);
    cudaGetSymbolAddress((void**)&pWfcSp, g_WfcSp);
    cudaGetSymbolAddress((void**)&pWcatSp, g_WcatSp);

    cudaFuncSetAttribute(tgemm_bf16,
                         cudaFuncAttributeMaxDynamicSharedMemorySize, 65536);
    const dim3 tsb(32, 8);

    // ---- prologue ----
    feat_mean_kernel<<<B_, 256>>>(features, pFM);

    // weight transpose + bf16 hi/lo split
    ts_split<<<dim3(ATTN_c / 32, ENC_Hc / 64), tsb>>>(W_u, ATTN_c, pWuSp, 0,
                                                      ENC_Hc / 2);
    ts_split<<<dim3(GDIM / 32, EMB_c / 64), tsb>>>(W_ih, GDIM, pWihSp, 0,
                                                   EMB_c / 2);
    ts_split<<<dim3(VOCAB_c / 32, DEC_Hc / 64), tsb>>>(W_fc, VOCAB_c, pWfcSp, 0,
                                                       DEC_Hc / 2);
    // Wcat = [W_ih rows 512.. ; W_hh] transposed+split
    ts_split<<<dim3(GDIM / 32, ENC_Hc / 64), tsb>>>(W_ih + (size_t)EMB_c * GDIM,
                                                    GDIM, pWcatSp, 0, XDIM / 2);
    ts_split<<<dim3(GDIM / 32, DEC_Hc / 64), tsb>>>(W_hh, GDIM, pWcatSp,
                                                    ENC_Hc / 2, XDIM / 2);

    // h0/c0 (tiny, fp32 path)
    sgemm128<<<dim3(1, DEC_Hc / 128), 256>>>(pFM, ENC_Hc, W_h0, DEC_Hc, ENC_Hc,
                                             b_h0, pH, B_);
    sgemm128<<<dim3(1, DEC_Hc / 128), 256>>>(pFM, ENC_Hc, W_c0, DEC_Hc, ENC_Hc,
                                             b_c0, pC, B_);

    // Uf = features @ W_u + b_u   [12544, 512]
    tgemm_bf16<<<dim3(B_ * NFEAT / 128, ATTN_c / 128, 1), 256, 65536>>>(
        features, ENC_Hc, pWuSp, ENC_Hc / 2, b_u, pUf, B_ * NFEAT, ATTN_c,
        ENC_Hc);

    // embeddings + Gemb = emb @ W_ih[:512] + b_ih   [1984, 4096]
    emb_gather_kernel<<<TSTEPS * B_, 128>>>(captions, emb_tab, pEA);
    tgemm_bf16<<<dim3((TSTEPS * B_ + 127) / 128, GDIM / 128, 1), 256, 65536>>>(
        pEA, EMB_c, pWihSp, EMB_c / 2, b_ih, pGE, TSTEPS * B_, GDIM, EMB_c);

    // ---- recurrence ----
    for (int t = 0; t < TSTEPS; t++) {
        attn_scores_kernel<<<B_, 512>>>(pUf, pH, W_w, b_w, W_a, pAl,
                                        outAttn ? outAttn + (size_t)t * NFEAT
                                                : nullptr);
        context_kernel<<<dim3(B_, 9), 256>>>(features, pAl, pH, pX);
        // gates: [64,3072] @ Wcat^T, split-K = 8 -> partials
        tgemm_bf16<<<dim3(1, GDIM / 128, SPLITK_GATES), 256, 65536>>>(
            pX, XDIM, pWcatSp, XDIM / 2, nullptr, pGP, B_, GDIM,
            XDIM / SPLITK_GATES);
        lstm_kernel<<<dim3(B_, 4), 256>>>(pGP, pGE + (size_t)t * B_ * GDIM,
                                          b_hh, pH, pC, pHA, t);
    }

    // ---- logits: [1984,1024] @ W_fc + b_fc ----
    tgemm_bf16<<<dim3((B_ * TSTEPS + 127) / 128, VOCAB_c / 128, 1), 256,
                 65536>>>(pHA, DEC_Hc, pWfcSp, DEC_Hc / 2, b_fc, outPred,
                          B_ * TSTEPS, VOCAB_c, DEC_Hc);
}

// round 5
// speedup vs baseline: 1.3804x; 1.0103x over previous
#include <cuda_runtime.h>
#include <cuda_bf16.h>
#include <math.h>
#include <stdint.h>

// Problem constants
#define B_      64
#define NFEAT   196
#define ENC_Hc  2048
#define DEC_Hc  1024
#define ATTN_c  512
#define EMB_c   512
#define VOCAB_c 32000
#define TSTEPS  31
#define XDIM    (ENC_Hc + DEC_Hc)   // 3072
#define GDIM    (4 * DEC_Hc)        // 4096
#define SPLITK_GATES 8

// ---------------- scratch (device globals; no allocation allowed) -----------
__device__ float g_Uf[(size_t)B_ * NFEAT * ATTN_c];
__device__ float g_featmean[B_ * ENC_Hc];
__device__ float g_h[B_ * DEC_Hc];
__device__ float g_c[B_ * DEC_Hc];
__device__ float g_hw[B_ * ATTN_c];
__device__ float g_scores[B_ * NFEAT];
__device__ float g_alpha[B_ * NFEAT];
__device__ float g_X[B_ * XDIM];
__device__ float g_GatesPart[SPLITK_GATES * B_ * GDIM];
__device__ float g_EmbAll[(size_t)TSTEPS * B_ * EMB_c];
__device__ float g_Gemb[(size_t)TSTEPS * B_ * GDIM];
__device__ float g_Hall[(size_t)B_ * TSTEPS * DEC_Hc];
// pre-split weights: [N][K/2] entries of {hi bf16x2, lo bf16x2}
__device__ uint2 g_WuSp[(size_t)ATTN_c * (ENC_Hc / 2)];
__device__ uint2 g_WihSp[(size_t)GDIM * (EMB_c / 2)];
__device__ uint2 g_WfcSp[(size_t)VOCAB_c * (DEC_Hc / 2)];
__device__ uint2 g_WcatSp[(size_t)GDIM * (XDIM / 2)];

// ---------------- bf16 pack helpers -----------------------------------------
__device__ __forceinline__ uint32_t pack_bf2(__nv_bfloat16 a, __nv_bfloat16 b) {
    union { __nv_bfloat162 v; uint32_t u; } cv;
    cv.v.x = a; cv.v.y = b;
    return cv.u;
}
__device__ __forceinline__ uint2 split_pack(float x0, float x1) {
    __nv_bfloat16 h0 = __float2bfloat16(x0);
    __nv_bfloat16 h1 = __float2bfloat16(x1);
    float l0 = x0 - __bfloat162float(h0);
    float l1 = x1 - __bfloat162float(h1);
    uint2 e;
    e.x = pack_bf2(h0, h1);
    e.y = pack_bf2(__float2bfloat16(l0), __float2bfloat16(l1));
    return e;
}
__device__ __forceinline__ int eidx(int row, int kp) {
    return row * 16 + ((kp + ((row & 3) << 2)) & 15);
}
__device__ __forceinline__ void mma_bf16(float* c, uint32_t a0, uint32_t a1,
                                         uint32_t a2, uint32_t a3,
                                         uint32_t b0, uint32_t b1) {
    asm volatile(
        "mma.sync.aligned.m16n8k16.row.col.f32.bf16.bf16.f32 "
        "{%0,%1,%2,%3}, {%4,%5,%6,%7}, {%8,%9}, {%0,%1,%2,%3};"
        : "+f"(c[0]), "+f"(c[1]), "+f"(c[2]), "+f"(c[3])
        : "r"(a0), "r"(a1), "r"(a2), "r"(a3), "r"(b0), "r"(b1));
}
__device__ __forceinline__ float tanh_fast(float x) {
    float y;
    asm("tanh.approx.f32 %0, %1;" : "=f"(y) : "f"(x));
    return y;
}

// =============== bf16x3 tensor GEMM: C = A @ Bsp^T (+bias) ==================
__global__ __launch_bounds__(256)
void tgemm_bf16(const float* __restrict__ A, int lda,
                const uint2* __restrict__ Bsp, int kpTot,
                const float* __restrict__ bias,
                float* __restrict__ C, int M, int N, int kLen)
{
    extern __shared__ uint2 sm[];
    uint2* bufA[2] = { sm,        sm + 4096 };
    uint2* bufB[2] = { sm + 2048, sm + 6144 };

    const int tid = threadIdx.x;
    const int lane = tid & 31, wid = tid >> 5;
    const int warp_mi = wid >> 1;
    const int warp_ni = wid & 1;
    const int rowBase = blockIdx.x * 128;
    const int colBase = blockIdx.y * 128;
    const int k0 = blockIdx.z * kLen;
    C += (size_t)blockIdx.z * M * N;

    const int sRow = tid >> 1;
    const int sKp8 = (tid & 1) * 8;
    const int aRowG = min(rowBase + sRow, M - 1);
    const float* Aptr = A + (size_t)aRowG * lda + k0;
    const uint2* Bptr = Bsp + (size_t)(colBase + sRow) * kpTot + (k0 >> 1);

    float acc[2][8][4];
#pragma unroll
    for (int mt = 0; mt < 2; mt++)
#pragma unroll
        for (int nt = 0; nt < 8; nt++)
#pragma unroll
            for (int q = 0; q < 4; q++) acc[mt][nt][q] = 0.f;

    const int nCh = kLen / 32;
    float2 rA[8];
    uint2  rB[8];

#pragma unroll
    for (int i = 0; i < 8; i++) {
        rA[i] = *(const float2*)(Aptr + (sKp8 + i) * 2);
        rB[i] = Bptr[sKp8 + i];
    }
#pragma unroll
    for (int i = 0; i < 8; i++) {
        bufA[0][eidx(sRow, sKp8 + i)] = split_pack(rA[i].x, rA[i].y);
        bufB[0][eidx(sRow, sKp8 + i)] = rB[i];
    }
    __syncthreads();

    for (int ch = 0; ch < nCh; ch++) {
        const int cur = ch & 1;
        if (ch + 1 < nCh) {
            const float* Ap2 = Aptr + (ch + 1) * 32;
            const uint2* Bp2 = Bptr + (ch + 1) * 16;
#pragma unroll
            for (int i = 0; i < 8; i++) {
                rA[i] = *(const float2*)(Ap2 + (sKp8 + i) * 2);
                rB[i] = Bp2[sKp8 + i];
            }
        }
#pragma unroll
        for (int k16 = 0; k16 < 2; k16++) {
            const int ak = k16 * 8 + (lane & 3);
            const int arl = warp_mi * 32 + (lane >> 2);
            uint2 af[2][4];
#pragma unroll
            for (int mt = 0; mt < 2; mt++) {
                const int r0 = arl + mt * 16;
                af[mt][0] = bufA[cur][eidx(r0,     ak)];
                af[mt][1] = bufA[cur][eidx(r0 + 8, ak)];
                af[mt][2] = bufA[cur][eidx(r0,     ak + 4)];
                af[mt][3] = bufA[cur][eidx(r0 + 8, ak + 4)];
            }
#pragma unroll
            for (int nt = 0; nt < 8; nt++) {
                const int nb = warp_ni * 64 + nt * 8 + (lane >> 2);
                const uint2 b0 = bufB[cur][eidx(nb, ak)];
                const uint2 b1 = bufB[cur][eidx(nb, ak + 4)];
#pragma unroll
                for (int mt = 0; mt < 2; mt++) {
                    mma_bf16(acc[mt][nt], af[mt][0].x, af[mt][1].x,
                             af[mt][2].x, af[mt][3].x, b0.x, b1.x);
                    mma_bf16(acc[mt][nt], af[mt][0].x, af[mt][1].x,
                             af[mt][2].x, af[mt][3].x, b0.y, b1.y);
                    mma_bf16(acc[mt][nt], af[mt][0].y, af[mt][1].y,
                             af[mt][2].y, af[mt][3].y, b0.x, b1.x);
                }
            }
        }
        if (ch + 1 < nCh) {
            const int nxt = cur ^ 1;
#pragma unroll
            for (int i = 0; i < 8; i++) {
                bufA[nxt][eidx(sRow, sKp8 + i)] = split_pack(rA[i].x, rA[i].y);
                bufB[nxt][eidx(sRow, sKp8 + i)] = rB[i];
            }
            __syncthreads();
        }
    }

#pragma unroll
    for (int mt = 0; mt < 2; mt++) {
#pragma unroll
        for (int nt = 0; nt < 8; nt++) {
            const int r0 = rowBase + warp_mi * 32 + mt * 16 + (lane >> 2);
            const int cc = colBase + warp_ni * 64 + nt * 8 + (lane & 3) * 2;
            float bv0 = 0.f, bv1 = 0.f;
            if (bias) { bv0 = bias[cc]; bv1 = bias[cc + 1]; }
            if (r0 < M) {
                float2 v = { acc[mt][nt][0] + bv0, acc[mt][nt][1] + bv1 };
                *(float2*)&C[(size_t)r0 * N + cc] = v;
            }
            if (r0 + 8 < M) {
                float2 v = { acc[mt][nt][2] + bv0, acc[mt][nt][3] + bv1 };
                *(float2*)&C[(size_t)(r0 + 8) * N + cc] = v;
            }
        }
    }
}

// =========== transpose + bf16 hi/lo split: in[K][N] -> out[N][kp] ===========
__global__ void ts_split(const float* __restrict__ in, int N,
                         uint2* __restrict__ out, int kpOff, int kpTot)
{
    __shared__ float t[64][33];
    const int n0 = blockIdx.x * 32, k0 = blockIdx.y * 64;
    const int tx = threadIdx.x, ty = threadIdx.y;
    for (int i = ty; i < 64; i += 8)
        t[i][tx] = in[(size_t)(k0 + i) * N + n0 + tx];
    __syncthreads();
    for (int i = ty; i < 32; i += 8) {
        out[(size_t)(n0 + tx) * kpTot + kpOff + (k0 >> 1) + i] =
            split_pack(t[2 * i][tx], t[2 * i + 1][tx]);
    }
}

// =============== fp32 fallback SGEMM (h0/c0 only, tiny) =====================
__global__ __launch_bounds__(256, 2)
void sgemm128(const float* __restrict__ A, int lda,
              const float* __restrict__ Bm, int N, int K,
              const float* __restrict__ bias,
              float* __restrict__ C, int M)
{
    __shared__ float As[2][16][132];
    __shared__ float Bs[2][16][128];
    const int tid = threadIdx.x;
    const int bm = blockIdx.x, bn = blockIdx.y;
    const int aRow = tid >> 1, aK = (tid & 1) * 8;
    const int bRow = tid >> 4, bCol = (tid & 15) * 4;
    const int rowBase = bm * 128;
    const int aRowG = min(rowBase + aRow, M - 1);
    const float* Ap = A + (size_t)aRowG * lda + aK;
    const float* Bp = Bm + (size_t)bRow * N + (size_t)bn * 128 + bCol;
    const int ty = tid >> 4, tx = tid & 15;
    float acc[8][8];
#pragma unroll
    for (int i = 0; i < 8; i++)
#pragma unroll
        for (int j = 0; j < 8; j++) acc[i][j] = 0.f;
    const int nTiles = K / 16;
    float4 pa0, pa1, pb0, pb1;
    pa0 = *(const float4*)(Ap); pa1 = *(const float4*)(Ap + 4);
    pb0 = *(const float4*)(Bp); pb1 = *(const float4*)(Bp + 64);
    As[0][aK+0][aRow]=pa0.x; As[0][aK+1][aRow]=pa0.y;
    As[0][aK+2][aRow]=pa0.z; As[0][aK+3][aRow]=pa0.w;
    As[0][aK+4][aRow]=pa1.x; As[0][aK+5][aRow]=pa1.y;
    As[0][aK+6][aRow]=pa1.z; As[0][aK+7][aRow]=pa1.w;
    *(float4*)&Bs[0][bRow][bCol]      = pb0;
    *(float4*)&Bs[0][bRow][bCol + 64] = pb1;
    __syncthreads();
    for (int t = 0; t < nTiles; t++) {
        const int cur = t & 1, nxt = cur ^ 1;
        if (t + 1 < nTiles) {
            const float* Ap2 = Ap + (t + 1) * 16;
            const float* Bp2 = Bp + (size_t)(t + 1) * 16 * N;
            pa0 = *(const float4*)(Ap2); pa1 = *(const float4*)(Ap2 + 4);
            pb0 = *(const float4*)(Bp2); pb1 = *(const float4*)(Bp2 + 64);
        }
#pragma unroll
        for (int k = 0; k < 16; k++) {
            float a[8], b[8];
            *(float4*)&a[0] = *(const float4*)&As[cur][k][ty * 8];
            *(float4*)&a[4] = *(const float4*)&As[cur][k][ty * 8 + 4];
            *(float4*)&b[0] = *(const float4*)&Bs[cur][k][tx * 8];
            *(float4*)&b[4] = *(const float4*)&Bs[cur][k][tx * 8 + 4];
#pragma unroll
            for (int i = 0; i < 8; i++)
#pragma unroll
                for (int j = 0; j < 8; j++) acc[i][j] += a[i] * b[j];
        }
        if (t + 1 < nTiles) {
            As[nxt][aK+0][aRow]=pa0.x; As[nxt][aK+1][aRow]=pa0.y;
            As[nxt][aK+2][aRow]=pa0.z; As[nxt][aK+3][aRow]=pa0.w;
            As[nxt][aK+4][aRow]=pa1.x; As[nxt][aK+5][aRow]=pa1.y;
            As[nxt][aK+6][aRow]=pa1.z; As[nxt][aK+7][aRow]=pa1.w;
            *(float4*)&Bs[nxt][bRow][bCol]      = pb0;
            *(float4*)&Bs[nxt][bRow][bCol + 64] = pb1;
            __syncthreads();
        }
    }
    const int r0 = rowBase + ty * 8;
    const int c0 = bn * 128 + tx * 8;
#pragma unroll
    for (int i = 0; i < 8; i++) {
        const int r = r0 + i;
        if (r < M) {
#pragma unroll
            for (int j = 0; j < 8; j++)
                C[(size_t)r * N + c0 + j] = acc[i][j] + bias[c0 + j];
        }
    }
}

// ---------------- misc small kernels ----------------------------------------
__global__ void feat_mean_kernel(const float* __restrict__ f,
                                 float* __restrict__ out)
{
    const int b = blockIdx.x;
    for (int k = threadIdx.x; k < ENC_Hc; k += blockDim.x) {
        float s = 0.f;
        for (int n = 0; n < NFEAT; n++)
            s += f[((size_t)b * NFEAT + n) * ENC_Hc + k];
        out[b * ENC_Hc + k] = s * (1.0f / (float)NFEAT);
    }
}

__global__ void emb_gather_kernel(const int* __restrict__ captions,
                                  const float* __restrict__ table,
                                  float* __restrict__ embAll)
{
    const int m = blockIdx.x;
    const int t = m >> 6, b = m & 63;
    const int cap = captions[b * 32 + t];
    const float4* src = (const float4*)(table + (size_t)cap * EMB_c);
    float4* dst = (float4*)(embAll + (size_t)m * EMB_c);
    for (int i = threadIdx.x; i < EMB_c / 4; i += blockDim.x) dst[i] = src[i];
}

// =============== hW = h @ W_w + b_w   (grid 64 x 2, 256 thr) ================
__global__ __launch_bounds__(256)
void hw_kernel(const float* __restrict__ h,
               const float* __restrict__ Ww,
               const float* __restrict__ bw,
               float* __restrict__ hw)
{
    const int b = blockIdx.x;
    const int k = blockIdx.y * 256 + threadIdx.x;
    __shared__ float sh[DEC_Hc];
    for (int j = threadIdx.x; j < DEC_Hc; j += 256) sh[j] = h[b * DEC_Hc + j];
    __syncthreads();
    float s0 = bw[k], s1 = 0.f, s2 = 0.f, s3 = 0.f;
#pragma unroll 4
    for (int j = 0; j < DEC_Hc; j += 4) {
        s0 += sh[j + 0] * Ww[(size_t)(j + 0) * ATTN_c + k];
        s1 += sh[j + 1] * Ww[(size_t)(j + 1) * ATTN_c + k];
        s2 += sh[j + 2] * Ww[(size_t)(j + 2) * ATTN_c + k];
        s3 += sh[j + 3] * Ww[(size_t)(j + 3) * ATTN_c + k];
    }
    hw[b * ATTN_c + k] = (s0 + s1) + (s2 + s3);
}

// =============== scores: grid (64, 7), 256 thr; tanh.approx =================
__global__ __launch_bounds__(256)
void scores_kernel(const float* __restrict__ Uf,
                   const float* __restrict__ hw,
                   const float* __restrict__ Wa,
                   float* __restrict__ scores)
{
    const int b = blockIdx.x, seg = blockIdx.y;
    const int tid = threadIdx.x;
    const int warp = tid >> 5, lane = tid & 31;
    __shared__ float shw[ATTN_c];
    __shared__ float swa[ATTN_c];
    for (int k = tid; k < ATTN_c; k += 256) {
        shw[k] = hw[b * ATTN_c + k];
        swa[k] = Wa[k];
    }
    __syncthreads();
#pragma unroll
    for (int r = warp; r < 28; r += 8) {
        const int n = seg * 28 + r;
        const float* uf = Uf + ((size_t)b * NFEAT + n) * ATTN_c;
        float s = 0.f;
#pragma unroll 4
        for (int k = lane; k < ATTN_c; k += 32)
            s += tanh_fast(uf[k] + shw[k]) * swa[k];
#pragma unroll
        for (int o = 16; o; o >>= 1) s += __shfl_xor_sync(0xffffffffu, s, o);
        if (lane == 0) scores[b * NFEAT + n] = s;
    }
}

// =============== softmax over 196 -> alpha (+attn out) ======================
__global__ __launch_bounds__(256)
void softmax_kernel(const float* __restrict__ scores,
                    float* __restrict__ alpha,
                    float* __restrict__ outAttn)
{
    const int b = blockIdx.x, tid = threadIdx.x;
    __shared__ float red[256];
    float v = (tid < NFEAT) ? scores[b * NFEAT + tid] : -INFINITY;
    red[tid] = v; __syncthreads();
    for (int o = 128; o; o >>= 1) {
        if (tid < o) red[tid] = fmaxf(red[tid], red[tid + o]);
        __syncthreads();
    }
    const float mx = red[0]; __syncthreads();
    const float e = (tid < NFEAT) ? __expf(v - mx) : 0.f;
    red[tid] = e; __syncthreads();
    for (int o = 128; o; o >>= 1) {
        if (tid < o) red[tid] += red[tid + o];
        __syncthreads();
    }
    const float inv = 1.f / red[0];
    if (tid < NFEAT) {
        const float a = e * inv;
        alpha[b * NFEAT + tid] = a;
        if (outAttn) outAttn[(size_t)b * TSTEPS * NFEAT + tid] = a;
    }
}

// =============== context = alpha @ features; X = [context | h] ==============
__global__ void context_kernel(const float* __restrict__ feat,
                               const float* __restrict__ alpha,
                               const float* __restrict__ h,
                               float* __restrict__ X)
{
    const int b = blockIdx.x, y = blockIdx.y, tid = threadIdx.x;
    if (y == 8) {
        for (int j = tid; j < DEC_Hc; j += 256)
            X[b * XDIM + ENC_Hc + j] = h[b * DEC_Hc + j];
        return;
    }
    __shared__ float sa[NFEAT];
    for (int n = tid; n < NFEAT; n += 256) sa[n] = alpha[b * NFEAT + n];
    __syncthreads();
    const int j = y * 256 + tid;
    float s = 0.f;
#pragma unroll 4
    for (int n = 0; n < NFEAT; n++)
        s += sa[n] * feat[((size_t)b * NFEAT + n) * ENC_Hc + j];
    X[b * XDIM + j] = s;
}

// =============== LSTM pointwise =============================================
__global__ void lstm_kernel(const float* __restrict__ P,
                            const float* __restrict__ GembT,
                            const float* __restrict__ bhh,
                            float* __restrict__ h,
                            float* __restrict__ c,
                            float* __restrict__ Hall, int t)
{
    const int b = blockIdx.x;
    const int j = blockIdx.y * 256 + threadIdx.x;
    const size_t ps = (size_t)B_ * GDIM;
    float g[4];
#pragma unroll
    for (int q = 0; q < 4; q++) {
        const int col = q * DEC_Hc + j;
        float s = GembT[(size_t)b * GDIM + col] + bhh[col];
#pragma unroll
        for (int z = 0; z < SPLITK_GATES; z++)
            s += P[z * ps + (size_t)b * GDIM + col];
        g[q] = s;
    }
    const float ig = 1.f / (1.f + __expf(-g[0]));
    const float fg = 1.f / (1.f + __expf(-g[1]));
    const float gg = tanhf(g[2]);
    const float og = 1.f / (1.f + __expf(-g[3]));
    const float cn = fg * c[b * DEC_Hc + j] + ig * gg;
    const float hn = og * tanhf(cn);
    c[b * DEC_Hc + j] = cn;
    h[b * DEC_Hc + j] = hn;
    Hall[((size_t)b * TSTEPS + t) * DEC_Hc + j] = hn;
}

// ---------------------------------------------------------------------------
extern "C" void kernel_launch(void* const* d_in, const int* in_sizes, int n_in,
                              void* d_out, int out_size)
{
    const float* features = (const float*)d_in[0];
    const int*   captions = (const int*)d_in[1];
    const float* emb_tab  = (const float*)d_in[2];
    const float* W_u  = (const float*)d_in[3];
    const float* b_u  = (const float*)d_in[4];
    const float* W_w  = (const float*)d_in[5];
    const float* b_w  = (const float*)d_in[6];
    const float* W_a  = (const float*)d_in[7];
    const float* W_ih = (const float*)d_in[9];
    const float* b_ih = (const float*)d_in[10];
    const float* W_hh = (const float*)d_in[11];
    const float* b_hh = (const float*)d_in[12];
    const float* W_fc = (const float*)d_in[13];
    const float* b_fc = (const float*)d_in[14];
    const float* W_h0 = (const float*)d_in[15];
    const float* b_h0 = (const float*)d_in[16];
    const float* W_c0 = (const float*)d_in[17];
    const float* b_c0 = (const float*)d_in[18];

    float* outPred = (float*)d_out;
    const size_t predElems = (size_t)B_ * TSTEPS * VOCAB_c;
    const size_t attnElems = (size_t)B_ * TSTEPS * NFEAT;
    float* outAttn =
        ((size_t)out_size >= predElems + attnElems) ? outPred + predElems : nullptr;

    float *pUf, *pFM, *pH, *pC, *pHW, *pSc, *pAl, *pX, *pGP, *pEA, *pGE, *pHA;
    uint2 *pWuSp, *pWihSp, *pWfcSp, *pWcatSp;
    cudaGetSymbolAddress((void**)&pUf, g_Uf);
    cudaGetSymbolAddress((void**)&pFM, g_featmean);
    cudaGetSymbolAddress((void**)&pH,  g_h);
    cudaGetSymbolAddress((void**)&pC,  g_c);
    cudaGetSymbolAddress((void**)&pHW, g_hw);
    cudaGetSymbolAddress((void**)&pSc, g_scores);
    cudaGetSymbolAddress((void**)&pAl, g_alpha);
    cudaGetSymbolAddress((void**)&pX,  g_X);
    cudaGetSymbolAddress((void**)&pGP, g_GatesPart);
    cudaGetSymbolAddress((void**)&pEA, g_EmbAll);
    cudaGetSymbolAddress((void**)&pGE, g_Gemb);
    cudaGetSymbolAddress((void**)&pHA, g_Hall);
    cudaGetSymbolAddress((void**)&pWuSp,  g_WuSp);
    cudaGetSymbolAddress((void**)&pWihSp, g_WihSp);
    cudaGetSymbolAddress((void**)&pWfcSp, g_WfcSp);
    cudaGetSymbolAddress((void**)&pWcatSp, g_WcatSp);

    cudaFuncSetAttribute(tgemm_bf16,
                         cudaFuncAttributeMaxDynamicSharedMemorySize, 65536);
    const dim3 tsb(32, 8);

    // ---- prologue (ordered so launch #4 = tgemm_bf16 Uf for ncu capture) ----
    feat_mean_kernel<<<B_, 256>>>(features, pFM);                       // 1
    ts_split<<<dim3(ATTN_c / 32, ENC_Hc / 64), tsb>>>(W_u, ATTN_c,
                                                      pWuSp, 0, ENC_Hc / 2); // 2
    sgemm128<<<dim3(1, DEC_Hc / 128), 256>>>(pFM, ENC_Hc, W_h0, DEC_Hc,
                                             ENC_Hc, b_h0, pH, B_);     // 3
    tgemm_bf16<<<dim3(B_ * NFEAT / 128, ATTN_c / 128, 1), 256, 65536>>>(
        features, ENC_Hc, pWuSp, ENC_Hc / 2, b_u, pUf, B_ * NFEAT, ATTN_c,
        ENC_Hc);                                                        // 4
    sgemm128<<<dim3(1, DEC_Hc / 128), 256>>>(pFM, ENC_Hc, W_c0, DEC_Hc,
                                             ENC_Hc, b_c0, pC, B_);     // 5
    ts_split<<<dim3(GDIM / 32, EMB_c / 64), tsb>>>(W_ih, GDIM, pWihSp, 0,
                                                   EMB_c / 2);
    ts_split<<<dim3(VOCAB_c / 32, DEC_Hc / 64), tsb>>>(W_fc, VOCAB_c, pWfcSp,
                                                       0, DEC_Hc / 2);
    ts_split<<<dim3(GDIM / 32, ENC_Hc / 64), tsb>>>(W_ih + (size_t)EMB_c * GDIM,
                                                    GDIM, pWcatSp, 0, XDIM / 2);
    ts_split<<<dim3(GDIM / 32, DEC_Hc / 64), tsb>>>(W_hh, GDIM, pWcatSp,
                                                    ENC_Hc / 2, XDIM / 2);
    emb_gather_kernel<<<TSTEPS * B_, 128>>>(captions, emb_tab, pEA);
    tgemm_bf16<<<dim3((TSTEPS * B_ + 127) / 128, GDIM / 128, 1), 256, 65536>>>(
        pEA, EMB_c, pWihSp, EMB_c / 2, b_ih, pGE, TSTEPS * B_, GDIM, EMB_c);

    // ---- recurrence ----
    for (int t = 0; t < TSTEPS; t++) {
        hw_kernel<<<dim3(B_, 2), 256>>>(pH, W_w, b_w, pHW);
        scores_kernel<<<dim3(B_, 7), 256>>>(pUf, pHW, W_a, pSc);
        softmax_kernel<<<B_, 256>>>(pSc, pAl,
                                    outAttn ? outAttn + (size_t)t * NFEAT
                                            : nullptr);
        context_kernel<<<dim3(B_, 9), 256>>>(features, pAl, pH, pX);
        tgemm_bf16<<<dim3(1, GDIM / 128, SPLITK_GATES), 256, 65536>>>(
            pX, XDIM, pWcatSp, XDIM / 2, nullptr, pGP, B_, GDIM,
            XDIM / SPLITK_GATES);
        lstm_kernel<<<dim3(B_, 4), 256>>>(pGP, pGE + (size_t)t * B_ * GDIM,
                                          b_hh, pH, pC, pHA, t);
    }

    // ---- logits: [1984,1024] @ W_fc + b_fc ----
    tgemm_bf16<<<dim3((B_ * TSTEPS + 127) / 128, VOCAB_c / 128, 1), 256,
                 65536>>>(pHA, DEC_Hc, pWfcSp, DEC_Hc / 2, b_fc, outPred,
                          B_ * TSTEPS, VOCAB_c, DEC_Hc);
}

// round 6
// speedup vs baseline: 1.8169x; 1.3162x over previous
#include <cuda_runtime.h>
#include <cuda_bf16.h>
#include <math.h>
#include <stdint.h>

// Problem constants
#define B_      64
#define NFEAT   196
#define ENC_Hc  2048
#define DEC_Hc  1024
#define ATTN_c  512
#define EMB_c   512
#define VOCAB_c 32000
#define TSTEPS  31
#define XDIM    (ENC_Hc + DEC_Hc)   // 3072
#define GDIM    (4 * DEC_Hc)        // 4096
#define SPLITK_GATES 8

// ---------------- scratch (device globals; no allocation allowed) -----------
__device__ float g_Uf[(size_t)B_ * NFEAT * ATTN_c];
__device__ float g_featmean[B_ * ENC_Hc];
__device__ float g_h[B_ * DEC_Hc];
__device__ float g_c[B_ * DEC_Hc];
__device__ float g_hw[B_ * ATTN_c];
__device__ float g_scores[B_ * NFEAT];
__device__ float g_alpha[B_ * NFEAT];
__device__ float g_GatesPart[SPLITK_GATES * B_ * GDIM];
__device__ float g_Gemb[(size_t)TSTEPS * B_ * GDIM];
// pre-split activations: [rows][K/2] of {hi bf16x2, lo bf16x2}
__device__ uint2 g_featSp[(size_t)B_ * NFEAT * (ENC_Hc / 2)];   // 102 MB
__device__ uint2 g_EmbSp[(size_t)TSTEPS * B_ * (EMB_c / 2)];
__device__ uint2 g_XSp[B_ * (XDIM / 2)];
__device__ uint2 g_HallSp[(size_t)B_ * TSTEPS * (DEC_Hc / 2)];
// pre-split weights: [N][K/2]
__device__ uint2 g_WuSp[(size_t)ATTN_c * (ENC_Hc / 2)];
__device__ uint2 g_WihSp[(size_t)GDIM * (EMB_c / 2)];
__device__ uint2 g_WfcSp[(size_t)VOCAB_c * (DEC_Hc / 2)];
__device__ uint2 g_WcatSp[(size_t)GDIM * (XDIM / 2)];

// ---------------- helpers ----------------------------------------------------
__device__ __forceinline__ uint32_t pack_bf2(__nv_bfloat16 a, __nv_bfloat16 b) {
    union { __nv_bfloat162 v; uint32_t u; } cv;
    cv.v.x = a; cv.v.y = b;
    return cv.u;
}
__device__ __forceinline__ uint2 split_pack(float x0, float x1) {
    __nv_bfloat16 h0 = __float2bfloat16(x0);
    __nv_bfloat16 h1 = __float2bfloat16(x1);
    float l0 = x0 - __bfloat162float(h0);
    float l1 = x1 - __bfloat162float(h1);
    uint2 e;
    e.x = pack_bf2(h0, h1);
    e.y = pack_bf2(__float2bfloat16(l0), __float2bfloat16(l1));
    return e;
}
__device__ __forceinline__ int eidx(int row, int kp) {
    return row * 16 + ((kp + ((row & 3) << 2)) & 15);
}
__device__ __forceinline__ void mma_bf16(float* c, uint32_t a0, uint32_t a1,
                                         uint32_t a2, uint32_t a3,
                                         uint32_t b0, uint32_t b1) {
    asm volatile(
        "mma.sync.aligned.m16n8k16.row.col.f32.bf16.bf16.f32 "
        "{%0,%1,%2,%3}, {%4,%5,%6,%7}, {%8,%9}, {%0,%1,%2,%3};"
        : "+f"(c[0]), "+f"(c[1]), "+f"(c[2]), "+f"(c[3])
        : "r"(a0), "r"(a1), "r"(a2), "r"(a3), "r"(b0), "r"(b1));
}
__device__ __forceinline__ float tanh_fast(float x) {
    float y;
    asm("tanh.approx.f32 %0, %1;" : "=f"(y) : "f"(x));
    return y;
}
__device__ __forceinline__ uint32_t smem_u32(const void* p) {
    uint32_t a;
    asm("{ .reg .u64 t; cvta.to.shared.u64 t, %1; cvt.u32.u64 %0, t; }"
        : "=r"(a) : "l"(p));
    return a;
}
__device__ __forceinline__ void cp_async8(uint32_t dst, const void* src) {
    asm volatile("cp.async.ca.shared.global [%0], [%1], 8;"
                 :: "r"(dst), "l"(src));
}
__device__ __forceinline__ uint2 lds64(uint32_t addr) {
    uint2 v;
    asm volatile("ld.shared.v2.u32 {%0,%1}, [%2];"
                 : "=r"(v.x), "=r"(v.y) : "r"(addr));
    return v;
}
#define CP_COMMIT() asm volatile("cp.async.commit_group;" ::: "memory")
#define CP_WAIT1()  asm volatile("cp.async.wait_group 1;" ::: "memory")

// ========== bf16x3 pipelined tensor GEMM: C = Asp @ Bsp^T (+bias) ===========
// Asp [M][kpA] uint2 (pre-split), Bsp [N][kpB] uint2. Tile MT x 128, k chunk 32,
// 3-stage cp.async pipeline. grid (ceil(M/MT), N/128, splits).
template <int MT>
__global__ __launch_bounds__(256, 2)
void tg(const uint2* __restrict__ Asp, int kpA,
        const uint2* __restrict__ Bsp, int kpB,
        const float* __restrict__ bias,
        float* __restrict__ C, int M, int N, int kLen)
{
    constexpr int WN = (MT == 128) ? 2 : 4;   // warps along n
    constexpr int NT = 128 / WN / 8;          // n frags per warp (8 or 4)
    constexpr int NBAND = 128 / WN;           // 64 or 32
    constexpr int EA = MT * 16;               // A entries per stage
    constexpr int NS = 3;
    constexpr int STAGE = EA + 2048;          // entries per stage

    extern __shared__ uint2 sm[];
    const uint32_t smBase = smem_u32(sm);

    const int tid = threadIdx.x;
    const int lane = tid & 31, wid = tid >> 5;
    const int warp_mi = wid / WN;
    const int warp_ni = wid % WN;
    const int rowBase = blockIdx.x * MT;
    const int colBase = blockIdx.y * 128;
    const int k0p = blockIdx.z * (kLen >> 1);
    C += (size_t)blockIdx.z * M * N;

    // A staging: ENT_A entries of 8B per thread
    constexpr int ENT_A = EA / 256;           // 8 or 4
    constexpr int TPR_A = 16 / ENT_A;         // threads per A row
    const int aRow = tid / TPR_A;
    const int aKp0 = (tid % TPR_A) * ENT_A;
    const int aRowG = min(rowBase + aRow, M - 1);
    const uint2* Agp = Asp + (size_t)aRowG * kpA + k0p + aKp0;
    // B staging: 8 entries per thread
    const int bRow = tid >> 1;
    const int bKp0 = (tid & 1) * 8;
    const uint2* Bgp = Bsp + (size_t)(colBase + bRow) * kpB + k0p + bKp0;

    float acc[2][NT][4];
#pragma unroll
    for (int mt = 0; mt < 2; mt++)
#pragma unroll
        for (int nt = 0; nt < NT; nt++)
#pragma unroll
            for (int q = 0; q < 4; q++) acc[mt][nt][q] = 0.f;

    const int nCh = kLen / 32;

    // issue stage for chunk ch into slot ch % NS
    auto issueStage = [&](int ch) {
        const int s = ch % NS;
        const uint32_t aB = smBase + (uint32_t)(s * STAGE) * 8;
        const uint32_t bB = aB + (uint32_t)EA * 8;
        const uint2* ag = Agp + ch * 16;
        const uint2* bg = Bgp + ch * 16;
#pragma unroll
        for (int i = 0; i < ENT_A; i++)
            cp_async8(aB + (uint32_t)eidx(aRow, aKp0 + i) * 8, ag + i);
#pragma unroll
        for (int i = 0; i < 8; i++)
            cp_async8(bB + (uint32_t)eidx(bRow, bKp0 + i) * 8, bg + i);
        CP_COMMIT();
    };

    issueStage(0);
    issueStage(1);

    for (int ch = 0; ch < nCh; ch++) {
        CP_WAIT1();            // chunk ch landed
        __syncthreads();       // all warps done with slot being overwritten
        if (ch + NS - 1 < nCh) issueStage(ch + NS - 1);

        const int s = ch % NS;
        const uint32_t aB = smBase + (uint32_t)(s * STAGE) * 8;
        const uint32_t bB = aB + (uint32_t)EA * 8;
#pragma unroll
        for (int k16 = 0; k16 < 2; k16++) {
            const int ak = k16 * 8 + (lane & 3);
            const int arl = warp_mi * 32 + (lane >> 2);
            uint2 af[2][4];
#pragma unroll
            for (int mt = 0; mt < 2; mt++) {
                const int r0 = arl + mt * 16;
                af[mt][0] = lds64(aB + (uint32_t)eidx(r0,     ak) * 8);
                af[mt][1] = lds64(aB + (uint32_t)eidx(r0 + 8, ak) * 8);
                af[mt][2] = lds64(aB + (uint32_t)eidx(r0,     ak + 4) * 8);
                af[mt][3] = lds64(aB + (uint32_t)eidx(r0 + 8, ak + 4) * 8);
            }
#pragma unroll
            for (int nt = 0; nt < NT; nt++) {
                const int nb = warp_ni * NBAND + nt * 8 + (lane >> 2);
                const uint2 b0 = lds64(bB + (uint32_t)eidx(nb, ak) * 8);
                const uint2 b1 = lds64(bB + (uint32_t)eidx(nb, ak + 4) * 8);
#pragma unroll
                for (int mt = 0; mt < 2; mt++) {
                    mma_bf16(acc[mt][nt], af[mt][0].x, af[mt][1].x,
                             af[mt][2].x, af[mt][3].x, b0.x, b1.x);
                    mma_bf16(acc[mt][nt], af[mt][0].x, af[mt][1].x,
                             af[mt][2].x, af[mt][3].x, b0.y, b1.y);
                    mma_bf16(acc[mt][nt], af[mt][0].y, af[mt][1].y,
                             af[mt][2].y, af[mt][3].y, b0.x, b1.x);
                }
            }
        }
    }

    // epilogue
#pragma unroll
    for (int mt = 0; mt < 2; mt++) {
#pragma unroll
        for (int nt = 0; nt < NT; nt++) {
            const int r0 = rowBase + warp_mi * 32 + mt * 16 + (lane >> 2);
            const int cc = colBase + warp_ni * NBAND + nt * 8 + (lane & 3) * 2;
            float bv0 = 0.f, bv1 = 0.f;
            if (bias) { bv0 = bias[cc]; bv1 = bias[cc + 1]; }
            if (r0 < M) {
                float2 v = { acc[mt][nt][0] + bv0, acc[mt][nt][1] + bv1 };
                *(float2*)&C[(size_t)r0 * N + cc] = v;
            }
            if (r0 + 8 < M) {
                float2 v = { acc[mt][nt][2] + bv0, acc[mt][nt][3] + bv1 };
                *(float2*)&C[(size_t)(r0 + 8) * N + cc] = v;
            }
        }
    }
}

// =========== transpose + split weights: in[K][N] -> out[N][kp] ==============
__global__ void ts_split(const float* __restrict__ in, int N,
                         uint2* __restrict__ out, int kpOff, int kpTot)
{
    __shared__ float t[64][33];
    const int n0 = blockIdx.x * 32, k0 = blockIdx.y * 64;
    const int tx = threadIdx.x, ty = threadIdx.y;
    for (int i = ty; i < 64; i += 8)
        t[i][tx] = in[(size_t)(k0 + i) * N + n0 + tx];
    __syncthreads();
    for (int i = ty; i < 32; i += 8) {
        out[(size_t)(n0 + tx) * kpTot + kpOff + (k0 >> 1) + i] =
            split_pack(t[2 * i][tx], t[2 * i + 1][tx]);
    }
}

// =========== elementwise fp32 -> split (row-major, same layout) =============
__global__ void row_split(const float* __restrict__ in,
                          uint2* __restrict__ out, size_t nPairs)
{
    const size_t i = (size_t)blockIdx.x * blockDim.x + threadIdx.x;
    if (i >= nPairs / 2) return;
    const float4 v = *(const float4*)(in + i * 4);
    out[i * 2]     = split_pack(v.x, v.y);
    out[i * 2 + 1] = split_pack(v.z, v.w);
}

// =============== fp32 SGEMM (h0/c0 only, tiny) ==============================
__global__ __launch_bounds__(256, 2)
void sgemm128(const float* __restrict__ A, int lda,
              const float* __restrict__ Bm, int N, int K,
              const float* __restrict__ bias,
              float* __restrict__ C, int M)
{
    __shared__ float As[2][16][132];
    __shared__ float Bs[2][16][128];
    const int tid = threadIdx.x;
    const int bm = blockIdx.x, bn = blockIdx.y;
    const int aRow = tid >> 1, aK = (tid & 1) * 8;
    const int bRow = tid >> 4, bCol = (tid & 15) * 4;
    const int rowBase = bm * 128;
    const int aRowG = min(rowBase + aRow, M - 1);
    const float* Ap = A + (size_t)aRowG * lda + aK;
    const float* Bp = Bm + (size_t)bRow * N + (size_t)bn * 128 + bCol;
    const int ty = tid >> 4, tx = tid & 15;
    float acc[8][8];
#pragma unroll
    for (int i = 0; i < 8; i++)
#pragma unroll
        for (int j = 0; j < 8; j++) acc[i][j] = 0.f;
    const int nTiles = K / 16;
    float4 pa0, pa1, pb0, pb1;
    pa0 = *(const float4*)(Ap); pa1 = *(const float4*)(Ap + 4);
    pb0 = *(const float4*)(Bp); pb1 = *(const float4*)(Bp + 64);
    As[0][aK+0][aRow]=pa0.x; As[0][aK+1][aRow]=pa0.y;
    As[0][aK+2][aRow]=pa0.z; As[0][aK+3][aRow]=pa0.w;
    As[0][aK+4][aRow]=pa1.x; As[0][aK+5][aRow]=pa1.y;
    As[0][aK+6][aRow]=pa1.z; As[0][aK+7][aRow]=pa1.w;
    *(float4*)&Bs[0][bRow][bCol]      = pb0;
    *(float4*)&Bs[0][bRow][bCol + 64] = pb1;
    __syncthreads();
    for (int t = 0; t < nTiles; t++) {
        const int cur = t & 1, nxt = cur ^ 1;
        if (t + 1 < nTiles) {
            const float* Ap2 = Ap + (t + 1) * 16;
            const float* Bp2 = Bp + (size_t)(t + 1) * 16 * N;
            pa0 = *(const float4*)(Ap2); pa1 = *(const float4*)(Ap2 + 4);
            pb0 = *(const float4*)(Bp2); pb1 = *(const float4*)(Bp2 + 64);
        }
#pragma unroll
        for (int k = 0; k < 16; k++) {
            float a[8], b[8];
            *(float4*)&a[0] = *(const float4*)&As[cur][k][ty * 8];
            *(float4*)&a[4] = *(const float4*)&As[cur][k][ty * 8 + 4];
            *(float4*)&b[0] = *(const float4*)&Bs[cur][k][tx * 8];
            *(float4*)&b[4] = *(const float4*)&Bs[cur][k][tx * 8 + 4];
#pragma unroll
            for (int i = 0; i < 8; i++)
#pragma unroll
                for (int j = 0; j < 8; j++) acc[i][j] += a[i] * b[j];
        }
        if (t + 1 < nTiles) {
            As[nxt][aK+0][aRow]=pa0.x; As[nxt][aK+1][aRow]=pa0.y;
            As[nxt][aK+2][aRow]=pa0.z; As[nxt][aK+3][aRow]=pa0.w;
            As[nxt][aK+4][aRow]=pa1.x; As[nxt][aK+5][aRow]=pa1.y;
            As[nxt][aK+6][aRow]=pa1.z; As[nxt][aK+7][aRow]=pa1.w;
            *(float4*)&Bs[nxt][bRow][bCol]      = pb0;
            *(float4*)&Bs[nxt][bRow][bCol + 64] = pb1;
            __syncthreads();
        }
    }
    const int r0 = rowBase + ty * 8;
    const int c0 = bn * 128 + tx * 8;
#pragma unroll
    for (int i = 0; i < 8; i++) {
        const int r = r0 + i;
        if (r < M) {
#pragma unroll
            for (int j = 0; j < 8; j++)
                C[(size_t)r * N + c0 + j] = acc[i][j] + bias[c0 + j];
        }
    }
}

// ---------------- misc small kernels ----------------------------------------
__global__ void feat_mean_kernel(const float* __restrict__ f,
                                 float* __restrict__ out)
{
    const int b = blockIdx.x;
    for (int k = threadIdx.x; k < ENC_Hc; k += blockDim.x) {
        float s = 0.f;
        for (int n = 0; n < NFEAT; n++)
            s += f[((size_t)b * NFEAT + n) * ENC_Hc + k];
        out[b * ENC_Hc + k] = s * (1.0f / (float)NFEAT);
    }
}

__global__ void emb_gather_kernel(const int* __restrict__ captions,
                                  const float* __restrict__ table,
                                  uint2* __restrict__ embSp)
{
    const int m = blockIdx.x;                 // t*64 + b
    const int t = m >> 6, b = m & 63;
    const int cap = captions[b * 32 + t];
    const float4* src = (const float4*)(table + (size_t)cap * EMB_c);
    uint2* dst = embSp + (size_t)m * (EMB_c / 2);
    for (int i = threadIdx.x; i < EMB_c / 4; i += blockDim.x) {
        const float4 v = src[i];
        dst[2 * i]     = split_pack(v.x, v.y);
        dst[2 * i + 1] = split_pack(v.z, v.w);
    }
}

// split h0 into XSp tail
__global__ void h0split_kernel(const float* __restrict__ h,
                               uint2* __restrict__ XSp)
{
    const int b = blockIdx.x, i = threadIdx.x;   // 512 threads
    XSp[(size_t)b * (XDIM / 2) + (ENC_Hc / 2) + i] =
        split_pack(h[b * DEC_Hc + 2 * i], h[b * DEC_Hc + 2 * i + 1]);
}

// =============== hW = h @ W_w + b_w =========================================
__global__ __launch_bounds__(256)
void hw_kernel(const float* __restrict__ h,
               const float* __restrict__ Ww,
               const float* __restrict__ bw,
               float* __restrict__ hw)
{
    const int b = blockIdx.x;
    const int k = blockIdx.y * 256 + threadIdx.x;
    __shared__ float sh[DEC_Hc];
    for (int j = threadIdx.x; j < DEC_Hc; j += 256) sh[j] = h[b * DEC_Hc + j];
    __syncthreads();
    float s0 = bw[k], s1 = 0.f, s2 = 0.f, s3 = 0.f;
#pragma unroll 4
    for (int j = 0; j < DEC_Hc; j += 4) {
        s0 += sh[j + 0] * Ww[(size_t)(j + 0) * ATTN_c + k];
        s1 += sh[j + 1] * Ww[(size_t)(j + 1) * ATTN_c + k];
        s2 += sh[j + 2] * Ww[(size_t)(j + 2) * ATTN_c + k];
        s3 += sh[j + 3] * Ww[(size_t)(j + 3) * ATTN_c + k];
    }
    hw[b * ATTN_c + k] = (s0 + s1) + (s2 + s3);
}

// =============== scores =====================================================
__global__ __launch_bounds__(256)
void scores_kernel(const float* __restrict__ Uf,
                   const float* __restrict__ hw,
                   const float* __restrict__ Wa,
                   float* __restrict__ scores)
{
    const int b = blockIdx.x, seg = blockIdx.y;
    const int tid = threadIdx.x;
    const int warp = tid >> 5, lane = tid & 31;
    __shared__ float shw[ATTN_c];
    __shared__ float swa[ATTN_c];
    for (int k = tid; k < ATTN_c; k += 256) {
        shw[k] = hw[b * ATTN_c + k];
        swa[k] = Wa[k];
    }
    __syncthreads();
#pragma unroll
    for (int r = warp; r < 28; r += 8) {
        const int n = seg * 28 + r;
        const float* uf = Uf + ((size_t)b * NFEAT + n) * ATTN_c;
        float s = 0.f;
#pragma unroll 4
        for (int k = lane; k < ATTN_c; k += 32)
            s += tanh_fast(uf[k] + shw[k]) * swa[k];
#pragma unroll
        for (int o = 16; o; o >>= 1) s += __shfl_xor_sync(0xffffffffu, s, o);
        if (lane == 0) scores[b * NFEAT + n] = s;
    }
}

// =============== softmax -> alpha (+attn out) ===============================
__global__ __launch_bounds__(256)
void softmax_kernel(const float* __restrict__ scores,
                    float* __restrict__ alpha,
                    float* __restrict__ outAttn)
{
    const int b = blockIdx.x, tid = threadIdx.x;
    __shared__ float red[256];
    float v = (tid < NFEAT) ? scores[b * NFEAT + tid] : -INFINITY;
    red[tid] = v; __syncthreads();
    for (int o = 128; o; o >>= 1) {
        if (tid < o) red[tid] = fmaxf(red[tid], red[tid + o]);
        __syncthreads();
    }
    const float mx = red[0]; __syncthreads();
    const float e = (tid < NFEAT) ? __expf(v - mx) : 0.f;
    red[tid] = e; __syncthreads();
    for (int o = 128; o; o >>= 1) {
        if (tid < o) red[tid] += red[tid + o];
        __syncthreads();
    }
    const float inv = 1.f / red[0];
    if (tid < NFEAT) {
        const float a = e * inv;
        alpha[b * NFEAT + tid] = a;
        if (outAttn) outAttn[(size_t)b * TSTEPS * NFEAT + tid] = a;
    }
}

// ======== context = alpha @ features -> XSp head (split), 2 cols/thread =====
__global__ __launch_bounds__(256)
void context_kernel(const float* __restrict__ feat,
                    const float* __restrict__ alpha,
                    uint2* __restrict__ XSp)
{
    const int b = blockIdx.x, y = blockIdx.y, tid = threadIdx.x;
    __shared__ float sa[NFEAT];
    for (int n = tid; n < NFEAT; n += 256) sa[n] = alpha[b * NFEAT + n];
    __syncthreads();
    const int j = y * 512 + tid * 2;
    float s0 = 0.f, s1 = 0.f;
    const float* fb = feat + (size_t)b * NFEAT * ENC_Hc + j;
#pragma unroll 4
    for (int n = 0; n < NFEAT; n++) {
        const float al = sa[n];
        const float2 fv = *(const float2*)(fb + (size_t)n * ENC_Hc);
        s0 += al * fv.x; s1 += al * fv.y;
    }
    XSp[(size_t)b * (XDIM / 2) + (j >> 1)] = split_pack(s0, s1);
}

// =============== LSTM pointwise: writes h, c, XSp tail, HallSp ==============
__global__ void lstm_kernel(const float* __restrict__ P,
                            const float* __restrict__ GembT,
                            const float* __restrict__ bhh,
                            float* __restrict__ h,
                            float* __restrict__ c,
                            uint2* __restrict__ XSp,
                            uint2* __restrict__ HallSp, int t)
{
    const int b = blockIdx.x;
    const int j = blockIdx.y * 256 + threadIdx.x;
    const size_t ps = (size_t)B_ * GDIM;
    float g[4];
#pragma unroll
    for (int q = 0; q < 4; q++) {
        const int col = q * DEC_Hc + j;
        float s = GembT[(size_t)b * GDIM + col] + bhh[col];
#pragma unroll
        for (int z = 0; z < SPLITK_GATES; z++)
            s += P[z * ps + (size_t)b * GDIM + col];
        g[q] = s;
    }
    const float ig = 1.f / (1.f + __expf(-g[0]));
    const float fg = 1.f / (1.f + __expf(-g[1]));
    const float gg = tanhf(g[2]);
    const float og = 1.f / (1.f + __expf(-g[3]));
    const float cn = fg * c[b * DEC_Hc + j] + ig * gg;
    const float hn = og * tanhf(cn);
    c[b * DEC_Hc + j] = cn;
    h[b * DEC_Hc + j] = hn;
    const float hn1 = __shfl_down_sync(0xffffffffu, hn, 1);
    if ((j & 1) == 0) {
        const uint2 e = split_pack(hn, hn1);
        HallSp[((size_t)b * TSTEPS + t) * (DEC_Hc / 2) + (j >> 1)] = e;
        XSp[(size_t)b * (XDIM / 2) + (ENC_Hc / 2) + (j >> 1)] = e;
    }
}

// ---------------------------------------------------------------------------
extern "C" void kernel_launch(void* const* d_in, const int* in_sizes, int n_in,
                              void* d_out, int out_size)
{
    const float* features = (const float*)d_in[0];
    const int*   captions = (const int*)d_in[1];
    const float* emb_tab  = (const float*)d_in[2];
    const float* W_u  = (const float*)d_in[3];
    const float* b_u  = (const float*)d_in[4];
    const float* W_w  = (const float*)d_in[5];
    const float* b_w  = (const float*)d_in[6];
    const float* W_a  = (const float*)d_in[7];
    const float* W_ih = (const float*)d_in[9];
    const float* b_ih = (const float*)d_in[10];
    const float* W_hh = (const float*)d_in[11];
    const float* b_hh = (const float*)d_in[12];
    const float* W_fc = (const float*)d_in[13];
    const float* b_fc = (const float*)d_in[14];
    const float* W_h0 = (const float*)d_in[15];
    const float* b_h0 = (const float*)d_in[16];
    const float* W_c0 = (const float*)d_in[17];
    const float* b_c0 = (const float*)d_in[18];

    float* outPred = (float*)d_out;
    const size_t predElems = (size_t)B_ * TSTEPS * VOCAB_c;
    const size_t attnElems = (size_t)B_ * TSTEPS * NFEAT;
    float* outAttn =
        ((size_t)out_size >= predElems + attnElems) ? outPred + predElems : nullptr;

    float *pUf, *pFM, *pH, *pC, *pHW, *pSc, *pAl, *pGP, *pGE;
    uint2 *pFSp, *pESp, *pXSp, *pHSp, *pWuSp, *pWihSp, *pWfcSp, *pWcatSp;
    cudaGetSymbolAddress((void**)&pUf, g_Uf);
    cudaGetSymbolAddress((void**)&pFM, g_featmean);
    cudaGetSymbolAddress((void**)&pH,  g_h);
    cudaGetSymbolAddress((void**)&pC,  g_c);
    cudaGetSymbolAddress((void**)&pHW, g_hw);
    cudaGetSymbolAddress((void**)&pSc, g_scores);
    cudaGetSymbolAddress((void**)&pAl, g_alpha);
    cudaGetSymbolAddress((void**)&pGP, g_GatesPart);
    cudaGetSymbolAddress((void**)&pGE, g_Gemb);
    cudaGetSymbolAddress((void**)&pFSp, g_featSp);
    cudaGetSymbolAddress((void**)&pESp, g_EmbSp);
    cudaGetSymbolAddress((void**)&pXSp, g_XSp);
    cudaGetSymbolAddress((void**)&pHSp, g_HallSp);
    cudaGetSymbolAddress((void**)&pWuSp,  g_WuSp);
    cudaGetSymbolAddress((void**)&pWihSp, g_WihSp);
    cudaGetSymbolAddress((void**)&pWfcSp, g_WfcSp);
    cudaGetSymbolAddress((void**)&pWcatSp, g_WcatSp);

    const int SM128 = 3 * (128 * 16 + 2048) * 8;   // 98304
    const int SM64  = 3 * (64 * 16 + 2048) * 8;    // 73728
    cudaFuncSetAttribute(tg<128>, cudaFuncAttributeMaxDynamicSharedMemorySize,
                         SM128);
    cudaFuncSetAttribute(tg<64>, cudaFuncAttributeMaxDynamicSharedMemorySize,
                         SM64);
    const dim3 tsb(32, 8);

    // ---- prologue (launch #4 = tg<128> Uf for ncu capture) ----
    feat_mean_kernel<<<B_, 256>>>(features, pFM);                         // 1
    row_split<<<(int)(((size_t)B_ * NFEAT * ENC_Hc / 4 + 255) / 256), 256>>>(
        features, pFSp, (size_t)B_ * NFEAT * (ENC_Hc / 2));               // 2
    ts_split<<<dim3(ATTN_c / 32, ENC_Hc / 64), tsb>>>(W_u, ATTN_c, pWuSp,
                                                      0, ENC_Hc / 2);     // 3
    tg<128><<<dim3(B_ * NFEAT / 128, ATTN_c / 128, 1), 256, SM128>>>(
        pFSp, ENC_Hc / 2, pWuSp, ENC_Hc / 2, b_u, pUf,
        B_ * NFEAT, ATTN_c, ENC_Hc);                                      // 4
    sgemm128<<<dim3(1, DEC_Hc / 128), 256>>>(pFM, ENC_Hc, W_h0, DEC_Hc,
                                             ENC_Hc, b_h0, pH, B_);
    sgemm128<<<dim3(1, DEC_Hc / 128), 256>>>(pFM, ENC_Hc, W_c0, DEC_Hc,
                                             ENC_Hc, b_c0, pC, B_);
    h0split_kernel<<<B_, 512>>>(pH, pXSp);
    ts_split<<<dim3(GDIM / 32, EMB_c / 64), tsb>>>(W_ih, GDIM, pWihSp, 0,
                                                   EMB_c / 2);
    ts_split<<<dim3(VOCAB_c / 32, DEC_Hc / 64), tsb>>>(W_fc, VOCAB_c, pWfcSp,
                                                       0, DEC_Hc / 2);
    ts_split<<<dim3(GDIM / 32, ENC_Hc / 64), tsb>>>(W_ih + (size_t)EMB_c * GDIM,
                                                    GDIM, pWcatSp, 0, XDIM / 2);
    ts_split<<<dim3(GDIM / 32, DEC_Hc / 64), tsb>>>(W_hh, GDIM, pWcatSp,
                                                    ENC_Hc / 2, XDIM / 2);
    emb_gather_kernel<<<TSTEPS * B_, 128>>>(captions, emb_tab, pESp);
    tg<128><<<dim3((TSTEPS * B_ + 127) / 128, GDIM / 128, 1), 256, SM128>>>(
        pESp, EMB_c / 2, pWihSp, EMB_c / 2, b_ih, pGE,
        TSTEPS * B_, GDIM, EMB_c);

    // ---- recurrence ----
    for (int t = 0; t < TSTEPS; t++) {
        hw_kernel<<<dim3(B_, 2), 256>>>(pH, W_w, b_w, pHW);
        scores_kernel<<<dim3(B_, 7), 256>>>(pUf, pHW, W_a, pSc);
        softmax_kernel<<<B_, 256>>>(pSc, pAl,
                                    outAttn ? outAttn + (size_t)t * NFEAT
                                            : nullptr);
        context_kernel<<<dim3(B_, ENC_Hc / 512), 256>>>(features, pAl, pXSp);
        tg<64><<<dim3(1, GDIM / 128, SPLITK_GATES), 256, SM64>>>(
            pXSp, XDIM / 2, pWcatSp, XDIM / 2, nullptr, pGP,
            B_, GDIM, XDIM / SPLITK_GATES);
        lstm_kernel<<<dim3(B_, 4), 256>>>(pGP, pGE + (size_t)t * B_ * GDIM,
                                          b_hh, pH, pC, pXSp, pHSp, t);
    }

    // ---- logits: HallSp[1984,1024] @ W_fc + b_fc ----
    tg<128><<<dim3((B_ * TSTEPS + 127) / 128, VOCAB_c / 128, 1), 256, SM128>>>(
        pHSp, DEC_Hc / 2, pWfcSp, DEC_Hc / 2, b_fc, outPred,
        B_ * TSTEPS, VOCAB_c, DEC_Hc);
}

// round 7
// speedup vs baseline: 2.0727x; 1.1408x over previous
#include <cuda_runtime.h>
#include <cuda_bf16.h>
#include <math.h>
#include <stdint.h>

// Problem constants
#define B_      64
#define NFEAT   196
#define ENC_Hc  2048
#define DEC_Hc  1024
#define ATTN_c  512
#define EMB_c   512
#define VOCAB_c 32000
#define TSTEPS  31
#define XDIM    (ENC_Hc + DEC_Hc)   // 3072
#define GDIM    (4 * DEC_Hc)        // 4096
#define SPLITK_GATES 8

// ---------------- scratch (device globals; no allocation allowed) -----------
// planar-chunked bf16x2 split format: per row of K elements -> K u32 words:
//   chunk c (32 k), hi pairs at [row*K + c*32 + 0..15], lo at [.. + 16..31]
__device__ float g_Uf[(size_t)B_ * NFEAT * ATTN_c];
__device__ float g_featmean[B_ * ENC_Hc];
__device__ float g_h[B_ * DEC_Hc];
__device__ float g_c[B_ * DEC_Hc];
__device__ float g_alpha[B_ * NFEAT];
__device__ float g_GatesPart[SPLITK_GATES * B_ * GDIM];
__device__ float g_Gemb[(size_t)TSTEPS * B_ * GDIM];
__device__ uint32_t g_featSp[(size_t)B_ * NFEAT * ENC_Hc];     // 102 MB
__device__ uint32_t g_EmbSp[(size_t)TSTEPS * B_ * EMB_c];
__device__ uint32_t g_XSp[B_ * XDIM];
__device__ uint32_t g_HallSp[(size_t)B_ * TSTEPS * DEC_Hc];
__device__ uint32_t g_WuSp[(size_t)ATTN_c * ENC_Hc];
__device__ uint32_t g_WihSp[(size_t)GDIM * EMB_c];
__device__ uint32_t g_WfcSp[(size_t)VOCAB_c * DEC_Hc];         // 131 MB
__device__ uint32_t g_WcatSp[(size_t)GDIM * XDIM];             // 48 MB

// ---------------- helpers ----------------------------------------------------
__device__ __forceinline__ uint32_t pack_bf2(__nv_bfloat16 a, __nv_bfloat16 b) {
    union { __nv_bfloat162 v; uint32_t u; } cv;
    cv.v.x = a; cv.v.y = b;
    return cv.u;
}
// store split pair (k even) into planar-chunked row
__device__ __forceinline__ void store_split(uint32_t* base, size_t row, int K,
                                            int k, float x0, float x1) {
    __nv_bfloat16 h0 = __float2bfloat16(x0);
    __nv_bfloat16 h1 = __float2bfloat16(x1);
    const float l0 = x0 - __bfloat162float(h0);
    const float l1 = x1 - __bfloat162float(h1);
    uint32_t* p = base + row * (size_t)K + ((k >> 5) << 5) + ((k & 31) >> 1);
    p[0]  = pack_bf2(h0, h1);
    p[16] = pack_bf2(__float2bfloat16(l0), __float2bfloat16(l1));
}
__device__ __forceinline__ void mma_bf16(float* c, uint32_t a0, uint32_t a1,
                                         uint32_t a2, uint32_t a3,
                                         uint32_t b0, uint32_t b1) {
    asm volatile(
        "mma.sync.aligned.m16n8k16.row.col.f32.bf16.bf16.f32 "
        "{%0,%1,%2,%3}, {%4,%5,%6,%7}, {%8,%9}, {%0,%1,%2,%3};"
        : "+f"(c[0]), "+f"(c[1]), "+f"(c[2]), "+f"(c[3])
        : "r"(a0), "r"(a1), "r"(a2), "r"(a3), "r"(b0), "r"(b1));
}
__device__ __forceinline__ void ldsm_x4(uint32_t& r0, uint32_t& r1,
                                        uint32_t& r2, uint32_t& r3,
                                        uint32_t addr) {
    asm volatile("ldmatrix.sync.aligned.m8n8.x4.shared.b16 {%0,%1,%2,%3}, [%4];"
                 : "=r"(r0), "=r"(r1), "=r"(r2), "=r"(r3) : "r"(addr));
}
__device__ __forceinline__ float tanh_fast(float x) {
    float y;
    asm("tanh.approx.f32 %0, %1;" : "=f"(y) : "f"(x));
    return y;
}
__device__ __forceinline__ uint32_t smem_u32(const void* p) {
    uint32_t a;
    asm("{ .reg .u64 t; cvta.to.shared.u64 t, %1; cvt.u32.u64 %0, t; }"
        : "=r"(a) : "l"(p));
    return a;
}
__device__ __forceinline__ void cp_async16(uint32_t dst, const void* src) {
    asm volatile("cp.async.cg.shared.global [%0], [%1], 16;"
                 :: "r"(dst), "l"(src));
}
#define CP_COMMIT() asm volatile("cp.async.commit_group;" ::: "memory")
#define CP_WAIT1()  asm volatile("cp.async.wait_group 1;" ::: "memory")

// ========== bf16x3 pipelined tensor GEMM with ldmatrix ======================
// A32/B32: planar-chunked split rows (KA/KB u32 per row). Tile MT x 128,
// k chunk 32, 3-stage cp.async. grid (ceil(M/MT), N/128, splits).
template <int MT>
__global__ __launch_bounds__(256, 2)
void tg(const uint32_t* __restrict__ A32, int KA,
        const uint32_t* __restrict__ B32, int KB,
        const float* __restrict__ bias,
        float* __restrict__ C, int M, int N, int kLen)
{
    constexpr int WN = (MT == 128) ? 2 : 4;     // warps along n
    constexpr int NT = 128 / WN / 8;            // 8 or 4 n-frags per warp
    constexpr int NBAND = 128 / WN;
    constexpr int A_UNITS = MT * 8;             // 16B units per stage
    constexpr int B_UNITS = 128 * 8;
    constexpr int NS = 3;
    constexpr int STAGE_B = (A_UNITS + B_UNITS) * 16;
    constexpr int APT = A_UNITS / 256;          // A units per thread (4 or 2)

    extern __shared__ uint32_t sm[];
    const uint32_t smBase = smem_u32(sm);

    const int tid = threadIdx.x;
    const int lane = tid & 31, wid = tid >> 5;
    const int warp_mi = wid / WN;
    const int warp_ni = wid % WN;
    const int rowBase = blockIdx.x * MT;
    const int colBase = blockIdx.y * 128;
    const int k0c = blockIdx.z * (kLen / 32);   // starting chunk
    C += (size_t)blockIdx.z * M * N;

    float acc[2][NT][4];
#pragma unroll
    for (int mt = 0; mt < 2; mt++)
#pragma unroll
        for (int nt = 0; nt < NT; nt++)
#pragma unroll
            for (int q = 0; q < 4; q++) acc[mt][nt][q] = 0.f;

    const int nCh = kLen / 32;

    auto issueStage = [&](int ch) {
        const int s = ch % NS;
        const uint32_t aB = smBase + s * STAGE_B;
        const uint32_t bB = aB + A_UNITS * 16;
        const size_t srcC = (size_t)(k0c + ch) * 32;
#pragma unroll
        for (int i = 0; i < APT; i++) {
            const int w = tid * APT + i;
            const int row = w >> 3, u = w & 7;
            const uint32_t* src =
                A32 + (size_t)min(rowBase + row, M - 1) * KA + srcC + u * 4;
            cp_async16(aB + (uint32_t)(row * 8 + (u ^ (row & 7))) * 16, src);
        }
#pragma unroll
        for (int i = 0; i < 4; i++) {
            const int w = tid * 4 + i;
            const int row = w >> 3, u = w & 7;
            const uint32_t* src =
                B32 + (size_t)(colBase + row) * KB + srcC + u * 4;
            cp_async16(bB + (uint32_t)(row * 8 + (u ^ (row & 7))) * 16, src);
        }
        CP_COMMIT();
    };

    issueStage(0);
    issueStage(1);

    // ldmatrix lane roles (constant per thread)
    const int aRowL = (lane & 15);              // row within m16 tile
    const int aUoff = (lane >> 4);              // 0/1 -> k-half unit
    const int bRowL = (lane & 7) + ((lane >> 4) << 3);  // row within n16
    const int bUoff = ((lane >> 3) & 1);

    for (int ch = 0; ch < nCh; ch++) {
        CP_WAIT1();
        __syncthreads();
        if (ch + 2 < nCh) issueStage(ch + 2); else CP_COMMIT();

        const int s = ch % NS;
        const uint32_t aB = smBase + s * STAGE_B;
        const uint32_t bB = aB + A_UNITS * 16;
#pragma unroll
        for (int t = 0; t < 2; t++) {
            uint32_t ah[2][4], al[2][4];
#pragma unroll
            for (int mt = 0; mt < 2; mt++) {
                const int r = warp_mi * 32 + mt * 16 + aRowL;
                const int uh = (2 * t + aUoff) ^ (r & 7);
                const int ul = (4 + 2 * t + aUoff) ^ (r & 7);
                ldsm_x4(ah[mt][0], ah[mt][1], ah[mt][2], ah[mt][3],
                        aB + (uint32_t)(r * 8 + uh) * 16);
                ldsm_x4(al[mt][0], al[mt][1], al[mt][2], al[mt][3],
                        aB + (uint32_t)(r * 8 + ul) * 16);
            }
#pragma unroll
            for (int np = 0; np < NT / 2; np++) {
                const int rb = warp_ni * NBAND + np * 16 + bRowL;
                const int uh = (2 * t + bUoff) ^ (rb & 7);
                const int ul = (4 + 2 * t + bUoff) ^ (rb & 7);
                uint32_t bh[4], bl[4];
                ldsm_x4(bh[0], bh[1], bh[2], bh[3],
                        bB + (uint32_t)(rb * 8 + uh) * 16);
                ldsm_x4(bl[0], bl[1], bl[2], bl[3],
                        bB + (uint32_t)(rb * 8 + ul) * 16);
#pragma unroll
                for (int half = 0; half < 2; half++) {
                    const int nt = np * 2 + half;
                    const uint32_t b0h = bh[half * 2], b1h = bh[half * 2 + 1];
                    const uint32_t b0l = bl[half * 2], b1l = bl[half * 2 + 1];
#pragma unroll
                    for (int mt = 0; mt < 2; mt++) {
                        mma_bf16(acc[mt][nt], ah[mt][0], ah[mt][1],
                                 ah[mt][2], ah[mt][3], b0h, b1h);
                        mma_bf16(acc[mt][nt], ah[mt][0], ah[mt][1],
                                 ah[mt][2], ah[mt][3], b0l, b1l);
                        mma_bf16(acc[mt][nt], al[mt][0], al[mt][1],
                                 al[mt][2], al[mt][3], b0h, b1h);
                    }
                }
            }
        }
    }

    // epilogue
#pragma unroll
    for (int mt = 0; mt < 2; mt++) {
#pragma unroll
        for (int nt = 0; nt < NT; nt++) {
            const int r0 = rowBase + warp_mi * 32 + mt * 16 + (lane >> 2);
            const int cc = colBase + warp_ni * NBAND + nt * 8 + (lane & 3) * 2;
            float bv0 = 0.f, bv1 = 0.f;
            if (bias) { bv0 = bias[cc]; bv1 = bias[cc + 1]; }
            if (r0 < M) {
                float2 v = { acc[mt][nt][0] + bv0, acc[mt][nt][1] + bv1 };
                *(float2*)&C[(size_t)r0 * N + cc] = v;
            }
            if (r0 + 8 < M) {
                float2 v = { acc[mt][nt][2] + bv0, acc[mt][nt][3] + bv1 };
                *(float2*)&C[(size_t)(r0 + 8) * N + cc] = v;
            }
        }
    }
}

// =========== transpose + split weights: in[K][N] -> out rows [N][K] =========
__global__ void ts_split(const float* __restrict__ in, int N,
                         uint32_t* __restrict__ out, int Ktot, int kOff)
{
    __shared__ float t[64][33];
    const int n0 = blockIdx.x * 32, k0 = blockIdx.y * 64;
    const int tx = threadIdx.x, ty = threadIdx.y;
    for (int i = ty; i < 64; i += 8)
        t[i][tx] = in[(size_t)(k0 + i) * N + n0 + tx];
    __syncthreads();
    for (int i = ty; i < 32; i += 8)
        store_split(out, n0 + tx, Ktot, kOff + k0 + 2 * i,
                    t[2 * i][tx], t[2 * i + 1][tx]);
}

// =========== row-major fp32 -> planar split (K = 2048 rows) =================
__global__ void row_split(const float* __restrict__ in,
                          uint32_t* __restrict__ out, size_t total)
{
    const size_t i = (size_t)blockIdx.x * blockDim.x + threadIdx.x;
    const size_t pos = i * 4;
    if (pos >= total) return;
    const float4 v = *(const float4*)(in + pos);
    const size_t row = pos >> 11;           // K = 2048
    const int k = (int)(pos & 2047);
    store_split(out, row, 2048, k,     v.x, v.y);
    store_split(out, row, 2048, k + 2, v.z, v.w);
}

// =============== fp32 SGEMM (h0/c0 only, tiny) ==============================
__global__ __launch_bounds__(256, 2)
void sgemm128(const float* __restrict__ A, int lda,
              const float* __restrict__ Bm, int N, int K,
              const float* __restrict__ bias,
              float* __restrict__ C, int M)
{
    __shared__ float As[2][16][132];
    __shared__ float Bs[2][16][128];
    const int tid = threadIdx.x;
    const int bm = blockIdx.x, bn = blockIdx.y;
    const int aRow = tid >> 1, aK = (tid & 1) * 8;
    const int bRow = tid >> 4, bCol = (tid & 15) * 4;
    const int rowBase = bm * 128;
    const int aRowG = min(rowBase + aRow, M - 1);
    const float* Ap = A + (size_t)aRowG * lda + aK;
    const float* Bp = Bm + (size_t)bRow * N + (size_t)bn * 128 + bCol;
    const int ty = tid >> 4, tx = tid & 15;
    float acc[8][8];
#pragma unroll
    for (int i = 0; i < 8; i++)
#pragma unroll
        for (int j = 0; j < 8; j++) acc[i][j] = 0.f;
    const int nTiles = K / 16;
    float4 pa0, pa1, pb0, pb1;
    pa0 = *(const float4*)(Ap); pa1 = *(const float4*)(Ap + 4);
    pb0 = *(const float4*)(Bp); pb1 = *(const float4*)(Bp + 64);
    As[0][aK+0][aRow]=pa0.x; As[0][aK+1][aRow]=pa0.y;
    As[0][aK+2][aRow]=pa0.z; As[0][aK+3][aRow]=pa0.w;
    As[0][aK+4][aRow]=pa1.x; As[0][aK+5][aRow]=pa1.y;
    As[0][aK+6][aRow]=pa1.z; As[0][aK+7][aRow]=pa1.w;
    *(float4*)&Bs[0][bRow][bCol]      = pb0;
    *(float4*)&Bs[0][bRow][bCol + 64] = pb1;
    __syncthreads();
    for (int t = 0; t < nTiles; t++) {
        const int cur = t & 1, nxt = cur ^ 1;
        if (t + 1 < nTiles) {
            const float* Ap2 = Ap + (t + 1) * 16;
            const float* Bp2 = Bp + (size_t)(t + 1) * 16 * N;
            pa0 = *(const float4*)(Ap2); pa1 = *(const float4*)(Ap2 + 4);
            pb0 = *(const float4*)(Bp2); pb1 = *(const float4*)(Bp2 + 64);
        }
#pragma unroll
        for (int k = 0; k < 16; k++) {
            float a[8], b[8];
            *(float4*)&a[0] = *(const float4*)&As[cur][k][ty * 8];
            *(float4*)&a[4] = *(const float4*)&As[cur][k][ty * 8 + 4];
            *(float4*)&b[0] = *(const float4*)&Bs[cur][k][tx * 8];
            *(float4*)&b[4] = *(const float4*)&Bs[cur][k][tx * 8 + 4];
#pragma unroll
            for (int i = 0; i < 8; i++)
#pragma unroll
                for (int j = 0; j < 8; j++) acc[i][j] += a[i] * b[j];
        }
        if (t + 1 < nTiles) {
            As[nxt][aK+0][aRow]=pa0.x; As[nxt][aK+1][aRow]=pa0.y;
            As[nxt][aK+2][aRow]=pa0.z; As[nxt][aK+3][aRow]=pa0.w;
            As[nxt][aK+4][aRow]=pa1.x; As[nxt][aK+5][aRow]=pa1.y;
            As[nxt][aK+6][aRow]=pa1.z; As[nxt][aK+7][aRow]=pa1.w;
            *(float4*)&Bs[nxt][bRow][bCol]      = pb0;
            *(float4*)&Bs[nxt][bRow][bCol + 64] = pb1;
            __syncthreads();
        }
    }
    const int r0 = rowBase + ty * 8;
    const int c0 = bn * 128 + tx * 8;
#pragma unroll
    for (int i = 0; i < 8; i++) {
        const int r = r0 + i;
        if (r < M) {
#pragma unroll
            for (int j = 0; j < 8; j++)
                C[(size_t)r * N + c0 + j] = acc[i][j] + bias[c0 + j];
        }
    }
}

// ---------------- misc small kernels ----------------------------------------
__global__ void feat_mean_kernel(const float* __restrict__ f,
                                 float* __restrict__ out)
{
    const int b = blockIdx.x;
    for (int k = threadIdx.x; k < ENC_Hc; k += blockDim.x) {
        float s = 0.f;
        for (int n = 0; n < NFEAT; n++)
            s += f[((size_t)b * NFEAT + n) * ENC_Hc + k];
        out[b * ENC_Hc + k] = s * (1.0f / (float)NFEAT);
    }
}

__global__ void emb_gather_kernel(const int* __restrict__ captions,
                                  const float* __restrict__ table,
                                  uint32_t* __restrict__ embSp)
{
    const int m = blockIdx.x;                 // t*64 + b
    const int t = m >> 6, b = m & 63;
    const int cap = captions[b * 32 + t];
    const float4* src = (const float4*)(table + (size_t)cap * EMB_c);
    for (int i = threadIdx.x; i < EMB_c / 4; i += blockDim.x) {
        const float4 v = src[i];
        store_split(embSp, m, EMB_c, 4 * i,     v.x, v.y);
        store_split(embSp, m, EMB_c, 4 * i + 2, v.z, v.w);
    }
}

__global__ void h0split_kernel(const float* __restrict__ h,
                               uint32_t* __restrict__ XSp)
{
    const int b = blockIdx.x, i = threadIdx.x;   // 512 threads
    store_split(XSp, b, XDIM, ENC_Hc + 2 * i,
                h[b * DEC_Hc + 2 * i], h[b * DEC_Hc + 2 * i + 1]);
}

// =============== fused attention: hW + scores + softmax =====================
__global__ __launch_bounds__(512)
void attn_kernel(const float* __restrict__ Uf,
                 const float* __restrict__ h,
                 const float* __restrict__ Ww,
                 const float* __restrict__ bw,
                 const float* __restrict__ Wa,
                 float* __restrict__ alpha,
                 float* __restrict__ outAttn)
{
    const int b = blockIdx.x;
    const int tid = threadIdx.x;
    __shared__ float sh[DEC_Hc];
    __shared__ float shw[ATTN_c];
    __shared__ float swa[ATTN_c];
    __shared__ float sa[256];
    __shared__ float red[512];

    for (int j = tid; j < DEC_Hc; j += 512) sh[j] = h[b * DEC_Hc + j];
    if (tid < ATTN_c) swa[tid] = Wa[tid];
    __syncthreads();
    if (tid < ATTN_c) {
        float s0 = bw[tid], s1 = 0.f, s2 = 0.f, s3 = 0.f;
#pragma unroll 4
        for (int j = 0; j < DEC_Hc; j += 4) {
            s0 += sh[j + 0] * Ww[(size_t)(j + 0) * ATTN_c + tid];
            s1 += sh[j + 1] * Ww[(size_t)(j + 1) * ATTN_c + tid];
            s2 += sh[j + 2] * Ww[(size_t)(j + 2) * ATTN_c + tid];
            s3 += sh[j + 3] * Ww[(size_t)(j + 3) * ATTN_c + tid];
        }
        shw[tid] = (s0 + s1) + (s2 + s3);
    }
    __syncthreads();
    const int warp = tid >> 5, lane = tid & 31;
    for (int n = warp; n < NFEAT; n += 16) {
        const float* uf = Uf + ((size_t)b * NFEAT + n) * ATTN_c;
        float s = 0.f;
#pragma unroll 4
        for (int k = lane; k < ATTN_c; k += 32)
            s += tanh_fast(uf[k] + shw[k]) * swa[k];
#pragma unroll
        for (int o = 16; o; o >>= 1) s += __shfl_xor_sync(0xffffffffu, s, o);
        if (lane == 0) sa[n] = s;
    }
    __syncthreads();
    float v = (tid < NFEAT) ? sa[tid] : -INFINITY;
    red[tid] = v; __syncthreads();
    for (int o = 256; o; o >>= 1) {
        if (tid < o) red[tid] = fmaxf(red[tid], red[tid + o]);
        __syncthreads();
    }
    const float mx = red[0]; __syncthreads();
    const float e = (tid < NFEAT) ? __expf(v - mx) : 0.f;
    red[tid] = e; __syncthreads();
    for (int o = 256; o; o >>= 1) {
        if (tid < o) red[tid] += red[tid + o];
        __syncthreads();
    }
    const float inv = 1.f / red[0];
    if (tid < NFEAT) {
        const float a = e * inv;
        alpha[b * NFEAT + tid] = a;
        if (outAttn) outAttn[(size_t)b * TSTEPS * NFEAT + tid] = a;
    }
}

// ======== context = alpha @ features -> XSp head (split) ====================
__global__ __launch_bounds__(256)
void context_kernel(const float* __restrict__ feat,
                    const float* __restrict__ alpha,
                    uint32_t* __restrict__ XSp)
{
    const int b = blockIdx.x, y = blockIdx.y, tid = threadIdx.x;
    __shared__ float sa[NFEAT];
    for (int n = tid; n < NFEAT; n += 256) sa[n] = alpha[b * NFEAT + n];
    __syncthreads();
    const int j = y * 512 + tid * 2;
    float s0 = 0.f, s1 = 0.f;
    const float* fb = feat + (size_t)b * NFEAT * ENC_Hc + j;
#pragma unroll 4
    for (int n = 0; n < NFEAT; n++) {
        const float al = sa[n];
        const float2 fv = *(const float2*)(fb + (size_t)n * ENC_Hc);
        s0 += al * fv.x; s1 += al * fv.y;
    }
    store_split(XSp, b, XDIM, j, s0, s1);
}

// =============== LSTM pointwise: h, c, XSp tail, HallSp =====================
__global__ void lstm_kernel(const float* __restrict__ P,
                            const float* __restrict__ GembT,
                            const float* __restrict__ bhh,
                            float* __restrict__ h,
                            float* __restrict__ c,
                            uint32_t* __restrict__ XSp,
                            uint32_t* __restrict__ HallSp, int t)
{
    const int b = blockIdx.x;
    const int j = blockIdx.y * 256 + threadIdx.x;
    const size_t ps = (size_t)B_ * GDIM;
    float g[4];
#pragma unroll
    for (int q = 0; q < 4; q++) {
        const int col = q * DEC_Hc + j;
        float s = GembT[(size_t)b * GDIM + col] + bhh[col];
#pragma unroll
        for (int z = 0; z < SPLITK_GATES; z++)
            s += P[z * ps + (size_t)b * GDIM + col];
        g[q] = s;
    }
    const float ig = 1.f / (1.f + __expf(-g[0]));
    const float fg = 1.f / (1.f + __expf(-g[1]));
    const float gg = tanhf(g[2]);
    const float og = 1.f / (1.f + __expf(-g[3]));
    const float cn = fg * c[b * DEC_Hc + j] + ig * gg;
    const float hn = og * tanhf(cn);
    c[b * DEC_Hc + j] = cn;
    h[b * DEC_Hc + j] = hn;
    const float hn1 = __shfl_down_sync(0xffffffffu, hn, 1);
    if ((j & 1) == 0) {
        store_split(HallSp, (size_t)b * TSTEPS + t, DEC_Hc, j, hn, hn1);
        store_split(XSp, b, XDIM, ENC_Hc + j, hn, hn1);
    }
}

// ---------------------------------------------------------------------------
extern "C" void kernel_launch(void* const* d_in, const int* in_sizes, int n_in,
                              void* d_out, int out_size)
{
    const float* features = (const float*)d_in[0];
    const int*   captions = (const int*)d_in[1];
    const float* emb_tab  = (const float*)d_in[2];
    const float* W_u  = (const float*)d_in[3];
    const float* b_u  = (const float*)d_in[4];
    const float* W_w  = (const float*)d_in[5];
    const float* b_w  = (const float*)d_in[6];
    const float* W_a  = (const float*)d_in[7];
    const float* W_ih = (const float*)d_in[9];
    const float* b_ih = (const float*)d_in[10];
    const float* W_hh = (const float*)d_in[11];
    const float* b_hh = (const float*)d_in[12];
    const float* W_fc = (const float*)d_in[13];
    const float* b_fc = (const float*)d_in[14];
    const float* W_h0 = (const float*)d_in[15];
    const float* b_h0 = (const float*)d_in[16];
    const float* W_c0 = (const float*)d_in[17];
    const float* b_c0 = (const float*)d_in[18];

    float* outPred = (float*)d_out;
    const size_t predElems = (size_t)B_ * TSTEPS * VOCAB_c;
    const size_t attnElems = (size_t)B_ * TSTEPS * NFEAT;
    float* outAttn =
        ((size_t)out_size >= predElems + attnElems) ? outPred + predElems : nullptr;

    float *pUf, *pFM, *pH, *pC, *pAl, *pGP, *pGE;
    uint32_t *pFSp, *pESp, *pXSp, *pHSp, *pWuSp, *pWihSp, *pWfcSp, *pWcatSp;
    cudaGetSymbolAddress((void**)&pUf, g_Uf);
    cudaGetSymbolAddress((void**)&pFM, g_featmean);
    cudaGetSymbolAddress((void**)&pH,  g_h);
    cudaGetSymbolAddress((void**)&pC,  g_c);
    cudaGetSymbolAddress((void**)&pAl, g_alpha);
    cudaGetSymbolAddress((void**)&pGP, g_GatesPart);
    cudaGetSymbolAddress((void**)&pGE, g_Gemb);
    cudaGetSymbolAddress((void**)&pFSp, g_featSp);
    cudaGetSymbolAddress((void**)&pESp, g_EmbSp);
    cudaGetSymbolAddress((void**)&pXSp, g_XSp);
    cudaGetSymbolAddress((void**)&pHSp, g_HallSp);
    cudaGetSymbolAddress((void**)&pWuSp,  g_WuSp);
    cudaGetSymbolAddress((void**)&pWihSp, g_WihSp);
    cudaGetSymbolAddress((void**)&pWfcSp, g_WfcSp);
    cudaGetSymbolAddress((void**)&pWcatSp, g_WcatSp);

    const int SM128 = 3 * (128 * 8 + 128 * 8) * 16;   // 98304
    const int SM64  = 3 * (64 * 8 + 128 * 8) * 16;    // 73728
    cudaFuncSetAttribute(tg<128>, cudaFuncAttributeMaxDynamicSharedMemorySize,
                         SM128);
    cudaFuncSetAttribute(tg<64>, cudaFuncAttributeMaxDynamicSharedMemorySize,
                         SM64);
    const dim3 tsb(32, 8);

    // ---- prologue (launch #4 = tg<128> Uf for ncu capture) ----
    feat_mean_kernel<<<B_, 256>>>(features, pFM);                         // 1
    row_split<<<(int)(((size_t)B_ * NFEAT * ENC_Hc / 4 + 255) / 256), 256>>>(
        features, pFSp, (size_t)B_ * NFEAT * ENC_Hc);                     // 2
    ts_split<<<dim3(ATTN_c / 32, ENC_Hc / 64), tsb>>>(W_u, ATTN_c, pWuSp,
                                                      ENC_Hc, 0);         // 3
    tg<128><<<dim3(B_ * NFEAT / 128, ATTN_c / 128, 1), 256, SM128>>>(
        pFSp, ENC_Hc, pWuSp, ENC_Hc, b_u, pUf, B_ * NFEAT, ATTN_c,
        ENC_Hc);                                                          // 4
    sgemm128<<<dim3(1, DEC_Hc / 128), 256>>>(pFM, ENC_Hc, W_h0, DEC_Hc,
                                             ENC_Hc, b_h0, pH, B_);
    sgemm128<<<dim3(1, DEC_Hc / 128), 256>>>(pFM, ENC_Hc, W_c0, DEC_Hc,
                                             ENC_Hc, b_c0, pC, B_);
    h0split_kernel<<<B_, 512>>>(pH, pXSp);
    ts_split<<<dim3(GDIM / 32, EMB_c / 64), tsb>>>(W_ih, GDIM, pWihSp,
                                                   EMB_c, 0);
    ts_split<<<dim3(VOCAB_c / 32, DEC_Hc / 64), tsb>>>(W_fc, VOCAB_c, pWfcSp,
                                                       DEC_Hc, 0);
    ts_split<<<dim3(GDIM / 32, ENC_Hc / 64), tsb>>>(W_ih + (size_t)EMB_c * GDIM,
                                                    GDIM, pWcatSp, XDIM, 0);
    ts_split<<<dim3(GDIM / 32, DEC_Hc / 64), tsb>>>(W_hh, GDIM, pWcatSp,
                                                    XDIM, ENC_Hc);
    emb_gather_kernel<<<TSTEPS * B_, 128>>>(captions, emb_tab, pESp);
    tg<128><<<dim3((TSTEPS * B_ + 127) / 128, GDIM / 128, 1), 256, SM128>>>(
        pESp, EMB_c, pWihSp, EMB_c, b_ih, pGE, TSTEPS * B_, GDIM, EMB_c);

    // ---- recurrence ----
    for (int t = 0; t < TSTEPS; t++) {
        attn_kernel<<<B_, 512>>>(pUf, pH, W_w, b_w, W_a, pAl,
                                 outAttn ? outAttn + (size_t)t * NFEAT
                                         : nullptr);
        context_kernel<<<dim3(B_, ENC_Hc / 512), 256>>>(features, pAl, pXSp);
        tg<64><<<dim3(1, GDIM / 128, SPLITK_GATES), 256, SM64>>>(
            pXSp, XDIM, pWcatSp, XDIM, nullptr, pGP,
            B_, GDIM, XDIM / SPLITK_GATES);
        lstm_kernel<<<dim3(B_, 4), 256>>>(pGP, pGE + (size_t)t * B_ * GDIM,
                                          b_hh, pH, pC, pXSp, pHSp, t);
    }

    // ---- logits: HallSp[1984,1024] @ W_fc + b_fc ----
    tg<128><<<dim3((B_ * TSTEPS + 127) / 128, VOCAB_c / 128, 1), 256, SM128>>>(
        pHSp, DEC_Hc, pWfcSp, DEC_Hc, b_fc, outPred,
        B_ * TSTEPS, VOCAB_c, DEC_Hc);
}

// round 8
// speedup vs baseline: 2.3901x; 1.1531x over previous
#include <cuda_runtime.h>
#include <cuda_bf16.h>
#include <math.h>
#include <stdint.h>

// Problem constants
#define B_      64
#define NFEAT   196
#define ENC_Hc  2048
#define DEC_Hc  1024
#define ATTN_c  512
#define EMB_c   512
#define VOCAB_c 32000
#define TSTEPS  31
#define XDIM    (ENC_Hc + DEC_Hc)   // 3072
#define GDIM    (4 * DEC_Hc)        // 4096
#define SPLITK_GATES 8

// ---------------- scratch (device globals; no allocation allowed) -----------
// planar-chunked bf16x2 split format: per row of K elements -> K u32 words:
//   chunk c (32 k), hi pairs at [row*K + c*32 + 0..15], lo at [.. + 16..31]
__device__ float g_Uf[(size_t)B_ * NFEAT * ATTN_c];
__device__ float g_featmean[B_ * ENC_Hc];
__device__ float g_h[B_ * DEC_Hc];
__device__ float g_c[B_ * DEC_Hc];
__device__ float g_alpha[B_ * NFEAT];
__device__ float g_GatesPart[SPLITK_GATES * B_ * GDIM];
__device__ float g_Gemb[(size_t)TSTEPS * B_ * GDIM];
__device__ uint32_t g_featSp[(size_t)B_ * NFEAT * ENC_Hc];     // 102 MB
__device__ uint32_t g_EmbSp[(size_t)TSTEPS * B_ * EMB_c];
__device__ uint32_t g_XSp[B_ * XDIM];
__device__ uint32_t g_HallSp[(size_t)TSTEPS * B_ * DEC_Hc];    // [t][b] rows!
__device__ uint32_t g_WuSp[(size_t)ATTN_c * ENC_Hc];
__device__ uint32_t g_WihSp[(size_t)GDIM * EMB_c];
__device__ uint32_t g_WfcSp[(size_t)VOCAB_c * DEC_Hc];         // 131 MB
__device__ uint32_t g_WcatSp[(size_t)GDIM * XDIM];             // 48 MB

// ---------------- helpers ----------------------------------------------------
__device__ __forceinline__ uint32_t pack_bf2(__nv_bfloat16 a, __nv_bfloat16 b) {
    union { __nv_bfloat162 v; uint32_t u; } cv;
    cv.v.x = a; cv.v.y = b;
    return cv.u;
}
__device__ __forceinline__ void store_split(uint32_t* base, size_t row, int K,
                                            int k, float x0, float x1) {
    __nv_bfloat16 h0 = __float2bfloat16(x0);
    __nv_bfloat16 h1 = __float2bfloat16(x1);
    const float l0 = x0 - __bfloat162float(h0);
    const float l1 = x1 - __bfloat162float(h1);
    uint32_t* p = base + row * (size_t)K + ((k >> 5) << 5) + ((k & 31) >> 1);
    p[0]  = pack_bf2(h0, h1);
    p[16] = pack_bf2(__float2bfloat16(l0), __float2bfloat16(l1));
}
__device__ __forceinline__ void mma_bf16(float* c, uint32_t a0, uint32_t a1,
                                         uint32_t a2, uint32_t a3,
                                         uint32_t b0, uint32_t b1) {
    asm volatile(
        "mma.sync.aligned.m16n8k16.row.col.f32.bf16.bf16.f32 "
        "{%0,%1,%2,%3}, {%4,%5,%6,%7}, {%8,%9}, {%0,%1,%2,%3};"
        : "+f"(c[0]), "+f"(c[1]), "+f"(c[2]), "+f"(c[3])
        : "r"(a0), "r"(a1), "r"(a2), "r"(a3), "r"(b0), "r"(b1));
}
__device__ __forceinline__ void ldsm_x4(uint32_t& r0, uint32_t& r1,
                                        uint32_t& r2, uint32_t& r3,
                                        uint32_t addr) {
    asm volatile("ldmatrix.sync.aligned.m8n8.x4.shared.b16 {%0,%1,%2,%3}, [%4];"
                 : "=r"(r0), "=r"(r1), "=r"(r2), "=r"(r3) : "r"(addr));
}
__device__ __forceinline__ float tanh_fast(float x) {
    float y;
    asm("tanh.approx.f32 %0, %1;" : "=f"(y) : "f"(x));
    return y;
}
__device__ __forceinline__ uint32_t smem_u32(const void* p) {
    uint32_t a;
    asm("{ .reg .u64 t; cvta.to.shared.u64 t, %1; cvt.u32.u64 %0, t; }"
        : "=r"(a) : "l"(p));
    return a;
}
__device__ __forceinline__ void cp_async16(uint32_t dst, const void* src) {
    asm volatile("cp.async.cg.shared.global [%0], [%1], 16;"
                 :: "r"(dst), "l"(src));
}
#define CP_COMMIT() asm volatile("cp.async.commit_group;" ::: "memory")
#define CP_WAIT1()  asm volatile("cp.async.wait_group 1;" ::: "memory")

// ========== bf16x3 pipelined tensor GEMM with ldmatrix ======================
// A32/B32: planar-chunked split rows (KA/KB u32 per row). Tile MT x 128,
// k chunk 32, 3-stage cp.async. grid (ceil(M/MT), N/128, splits).
// C row stride = ldc; split z writes to C + z*M*ldc.
template <int MT>
__global__ __launch_bounds__(256, 2)
void tg(const uint32_t* __restrict__ A32, int KA,
        const uint32_t* __restrict__ B32, int KB,
        const float* __restrict__ bias,
        float* __restrict__ C, int M, int N, int ldc, int kLen)
{
    constexpr int WN = (MT == 128) ? 2 : 4;
    constexpr int NT = 128 / WN / 8;
    constexpr int NBAND = 128 / WN;
    constexpr int A_UNITS = MT * 8;
    constexpr int B_UNITS = 128 * 8;
    constexpr int NS = 3;
    constexpr int STAGE_B = (A_UNITS + B_UNITS) * 16;
    constexpr int APT = A_UNITS / 256;

    extern __shared__ uint32_t sm[];
    const uint32_t smBase = smem_u32(sm);

    const int tid = threadIdx.x;
    const int lane = tid & 31, wid = tid >> 5;
    const int warp_mi = wid / WN;
    const int warp_ni = wid % WN;
    const int rowBase = blockIdx.x * MT;
    const int colBase = blockIdx.y * 128;
    const int k0c = blockIdx.z * (kLen / 32);
    C += (size_t)blockIdx.z * M * ldc;

    float acc[2][NT][4];
#pragma unroll
    for (int mt = 0; mt < 2; mt++)
#pragma unroll
        for (int nt = 0; nt < NT; nt++)
#pragma unroll
            for (int q = 0; q < 4; q++) acc[mt][nt][q] = 0.f;

    const int nCh = kLen / 32;

    auto issueStage = [&](int ch) {
        const int s = ch % NS;
        const uint32_t aB = smBase + s * STAGE_B;
        const uint32_t bB = aB + A_UNITS * 16;
        const size_t srcC = (size_t)(k0c + ch) * 32;
#pragma unroll
        for (int i = 0; i < APT; i++) {
            const int w = tid * APT + i;
            const int row = w >> 3, u = w & 7;
            const uint32_t* src =
                A32 + (size_t)min(rowBase + row, M - 1) * KA + srcC + u * 4;
            cp_async16(aB + (uint32_t)(row * 8 + (u ^ (row & 7))) * 16, src);
        }
#pragma unroll
        for (int i = 0; i < 4; i++) {
            const int w = tid * 4 + i;
            const int row = w >> 3, u = w & 7;
            const uint32_t* src =
                B32 + (size_t)(colBase + row) * KB + srcC + u * 4;
            cp_async16(bB + (uint32_t)(row * 8 + (u ^ (row & 7))) * 16, src);
        }
        CP_COMMIT();
    };

    issueStage(0);
    issueStage(1);

    const int aRowL = (lane & 15);
    const int aUoff = (lane >> 4);
    const int bRowL = (lane & 7) + ((lane >> 4) << 3);
    const int bUoff = ((lane >> 3) & 1);

    for (int ch = 0; ch < nCh; ch++) {
        CP_WAIT1();
        __syncthreads();
        if (ch + 2 < nCh) issueStage(ch + 2); else CP_COMMIT();

        const int s = ch % NS;
        const uint32_t aB = smBase + s * STAGE_B;
        const uint32_t bB = aB + A_UNITS * 16;
#pragma unroll
        for (int t = 0; t < 2; t++) {
            uint32_t ah[2][4], al[2][4];
#pragma unroll
            for (int mt = 0; mt < 2; mt++) {
                const int r = warp_mi * 32 + mt * 16 + aRowL;
                const int uh = (2 * t + aUoff) ^ (r & 7);
                const int ul = (4 + 2 * t + aUoff) ^ (r & 7);
                ldsm_x4(ah[mt][0], ah[mt][1], ah[mt][2], ah[mt][3],
                        aB + (uint32_t)(r * 8 + uh) * 16);
                ldsm_x4(al[mt][0], al[mt][1], al[mt][2], al[mt][3],
                        aB + (uint32_t)(r * 8 + ul) * 16);
            }
#pragma unroll
            for (int np = 0; np < NT / 2; np++) {
                const int rb = warp_ni * NBAND + np * 16 + bRowL;
                const int uh = (2 * t + bUoff) ^ (rb & 7);
                const int ul = (4 + 2 * t + bUoff) ^ (rb & 7);
                uint32_t bh[4], bl[4];
                ldsm_x4(bh[0], bh[1], bh[2], bh[3],
                        bB + (uint32_t)(rb * 8 + uh) * 16);
                ldsm_x4(bl[0], bl[1], bl[2], bl[3],
                        bB + (uint32_t)(rb * 8 + ul) * 16);
#pragma unroll
                for (int half = 0; half < 2; half++) {
                    const int nt = np * 2 + half;
                    const uint32_t b0h = bh[half * 2], b1h = bh[half * 2 + 1];
                    const uint32_t b0l = bl[half * 2], b1l = bl[half * 2 + 1];
#pragma unroll
                    for (int mt = 0; mt < 2; mt++) {
                        mma_bf16(acc[mt][nt], ah[mt][0], ah[mt][1],
                                 ah[mt][2], ah[mt][3], b0h, b1h);
                        mma_bf16(acc[mt][nt], ah[mt][0], ah[mt][1],
                                 ah[mt][2], ah[mt][3], b0l, b1l);
                        mma_bf16(acc[mt][nt], al[mt][0], al[mt][1],
                                 al[mt][2], al[mt][3], b0h, b1h);
                    }
                }
            }
        }
    }

    // epilogue
#pragma unroll
    for (int mt = 0; mt < 2; mt++) {
#pragma unroll
        for (int nt = 0; nt < NT; nt++) {
            const int r0 = rowBase + warp_mi * 32 + mt * 16 + (lane >> 2);
            const int cc = colBase + warp_ni * NBAND + nt * 8 + (lane & 3) * 2;
            float bv0 = 0.f, bv1 = 0.f;
            if (bias) { bv0 = bias[cc]; bv1 = bias[cc + 1]; }
            if (r0 < M) {
                float2 v = { acc[mt][nt][0] + bv0, acc[mt][nt][1] + bv1 };
                *(float2*)&C[(size_t)r0 * ldc + cc] = v;
            }
            if (r0 + 8 < M) {
                float2 v = { acc[mt][nt][2] + bv0, acc[mt][nt][3] + bv1 };
                *(float2*)&C[(size_t)(r0 + 8) * ldc + cc] = v;
            }
        }
    }
}

// =========== transpose + split weights: in[K][N] -> out rows [N][K] =========
__global__ void ts_split(const float* __restrict__ in, int N,
                         uint32_t* __restrict__ out, int Ktot, int kOff)
{
    __shared__ float t[64][33];
    const int n0 = blockIdx.x * 32, k0 = blockIdx.y * 64;
    const int tx = threadIdx.x, ty = threadIdx.y;
    for (int i = ty; i < 64; i += 8)
        t[i][tx] = in[(size_t)(k0 + i) * N + n0 + tx];
    __syncthreads();
    for (int i = ty; i < 32; i += 8)
        store_split(out, n0 + tx, Ktot, kOff + k0 + 2 * i,
                    t[2 * i][tx], t[2 * i + 1][tx]);
}

// =========== row-major fp32 -> planar split (K = 2048 rows) =================
__global__ void row_split(const float* __restrict__ in,
                          uint32_t* __restrict__ out, size_t total)
{
    const size_t i = (size_t)blockIdx.x * blockDim.x + threadIdx.x;
    const size_t pos = i * 4;
    if (pos >= total) return;
    const float4 v = *(const float4*)(in + pos);
    const size_t row = pos >> 11;
    const int k = (int)(pos & 2047);
    store_split(out, row, 2048, k,     v.x, v.y);
    store_split(out, row, 2048, k + 2, v.z, v.w);
}

// =============== fp32 SGEMM (h0/c0 only, tiny) ==============================
__global__ __launch_bounds__(256, 2)
void sgemm128(const float* __restrict__ A, int lda,
              const float* __restrict__ Bm, int N, int K,
              const float* __restrict__ bias,
              float* __restrict__ C, int M)
{
    __shared__ float As[2][16][132];
    __shared__ float Bs[2][16][128];
    const int tid = threadIdx.x;
    const int bm = blockIdx.x, bn = blockIdx.y;
    const int aRow = tid >> 1, aK = (tid & 1) * 8;
    const int bRow = tid >> 4, bCol = (tid & 15) * 4;
    const int rowBase = bm * 128;
    const int aRowG = min(rowBase + aRow, M - 1);
    const float* Ap = A + (size_t)aRowG * lda + aK;
    const float* Bp = Bm + (size_t)bRow * N + (size_t)bn * 128 + bCol;
    const int ty = tid >> 4, tx = tid & 15;
    float acc[8][8];
#pragma unroll
    for (int i = 0; i < 8; i++)
#pragma unroll
        for (int j = 0; j < 8; j++) acc[i][j] = 0.f;
    const int nTiles = K / 16;
    float4 pa0, pa1, pb0, pb1;
    pa0 = *(const float4*)(Ap); pa1 = *(const float4*)(Ap + 4);
    pb0 = *(const float4*)(Bp); pb1 = *(const float4*)(Bp + 64);
    As[0][aK+0][aRow]=pa0.x; As[0][aK+1][aRow]=pa0.y;
    As[0][aK+2][aRow]=pa0.z; As[0][aK+3][aRow]=pa0.w;
    As[0][aK+4][aRow]=pa1.x; As[0][aK+5][aRow]=pa1.y;
    As[0][aK+6][aRow]=pa1.z; As[0][aK+7][aRow]=pa1.w;
    *(float4*)&Bs[0][bRow][bCol]      = pb0;
    *(float4*)&Bs[0][bRow][bCol + 64] = pb1;
    __syncthreads();
    for (int t = 0; t < nTiles; t++) {
        const int cur = t & 1, nxt = cur ^ 1;
        if (t + 1 < nTiles) {
            const float* Ap2 = Ap + (t + 1) * 16;
            const float* Bp2 = Bp + (size_t)(t + 1) * 16 * N;
            pa0 = *(const float4*)(Ap2); pa1 = *(const float4*)(Ap2 + 4);
            pb0 = *(const float4*)(Bp2); pb1 = *(const float4*)(Bp2 + 64);
        }
#pragma unroll
        for (int k = 0; k < 16; k++) {
            float a[8], b[8];
            *(float4*)&a[0] = *(const float4*)&As[cur][k][ty * 8];
            *(float4*)&a[4] = *(const float4*)&As[cur][k][ty * 8 + 4];
            *(float4*)&b[0] = *(const float4*)&Bs[cur][k][tx * 8];
            *(float4*)&b[4] = *(const float4*)&Bs[cur][k][tx * 8 + 4];
#pragma unroll
            for (int i = 0; i < 8; i++)
#pragma unroll
                for (int j = 0; j < 8; j++) acc[i][j] += a[i] * b[j];
        }
        if (t + 1 < nTiles) {
            As[nxt][aK+0][aRow]=pa0.x; As[nxt][aK+1][aRow]=pa0.y;
            As[nxt][aK+2][aRow]=pa0.z; As[nxt][aK+3][aRow]=pa0.w;
            As[nxt][aK+4][aRow]=pa1.x; As[nxt][aK+5][aRow]=pa1.y;
            As[nxt][aK+6][aRow]=pa1.z; As[nxt][aK+7][aRow]=pa1.w;
            *(float4*)&Bs[nxt][bRow][bCol]      = pb0;
            *(float4*)&Bs[nxt][bRow][bCol + 64] = pb1;
            __syncthreads();
        }
    }
    const int r0 = rowBase + ty * 8;
    const int c0 = bn * 128 + tx * 8;
#pragma unroll
    for (int i = 0; i < 8; i++) {
        const int r = r0 + i;
        if (r < M) {
#pragma unroll
            for (int j = 0; j < 8; j++)
                C[(size_t)r * N + c0 + j] = acc[i][j] + bias[c0 + j];
        }
    }
}

// ---------------- misc small kernels ----------------------------------------
__global__ void feat_mean_kernel(const float* __restrict__ f,
                                 float* __restrict__ out)
{
    const int b = blockIdx.x;
    const int k = blockIdx.y * 256 + threadIdx.x;
    float s = 0.f;
#pragma unroll 4
    for (int n = 0; n < NFEAT; n++)
        s += f[((size_t)b * NFEAT + n) * ENC_Hc + k];
    out[b * ENC_Hc + k] = s * (1.0f / (float)NFEAT);
}

__global__ void emb_gather_kernel(const int* __restrict__ captions,
                                  const float* __restrict__ table,
                                  uint32_t* __restrict__ embSp)
{
    const int m = blockIdx.x;
    const int t = m >> 6, b = m & 63;
    const int cap = captions[b * 32 + t];
    const float4* src = (const float4*)(table + (size_t)cap * EMB_c);
    for (int i = threadIdx.x; i < EMB_c / 4; i += blockDim.x) {
        const float4 v = src[i];
        store_split(embSp, m, EMB_c, 4 * i,     v.x, v.y);
        store_split(embSp, m, EMB_c, 4 * i + 2, v.z, v.w);
    }
}

__global__ void h0split_kernel(const float* __restrict__ h,
                               uint32_t* __restrict__ XSp)
{
    const int b = blockIdx.x, i = threadIdx.x;
    store_split(XSp, b, XDIM, ENC_Hc + 2 * i,
                h[b * DEC_Hc + 2 * i], h[b * DEC_Hc + 2 * i + 1]);
}

// =============== fused attention: hW + scores + softmax =====================
__global__ __launch_bounds__(512)
void attn_kernel(const float* __restrict__ Uf,
                 const float* __restrict__ h,
                 const float* __restrict__ Ww,
                 const float* __restrict__ bw,
                 const float* __restrict__ Wa,
                 float* __restrict__ alpha,
                 float* __restrict__ outAttn)
{
    const int b = blockIdx.x;
    const int tid = threadIdx.x;
    __shared__ float sh[DEC_Hc];
    __shared__ float shw[ATTN_c];
    __shared__ float swa[ATTN_c];
    __shared__ float sa[256];
    __shared__ float red[512];

    for (int j = tid; j < DEC_Hc; j += 512) sh[j] = h[b * DEC_Hc + j];
    if (tid < ATTN_c) swa[tid] = Wa[tid];
    __syncthreads();
    if (tid < ATTN_c) {
        float s0 = bw[tid], s1 = 0.f, s2 = 0.f, s3 = 0.f;
#pragma unroll 4
        for (int j = 0; j < DEC_Hc; j += 4) {
            s0 += sh[j + 0] * Ww[(size_t)(j + 0) * ATTN_c + tid];
            s1 += sh[j + 1] * Ww[(size_t)(j + 1) * ATTN_c + tid];
            s2 += sh[j + 2] * Ww[(size_t)(j + 2) * ATTN_c + tid];
            s3 += sh[j + 3] * Ww[(size_t)(j + 3) * ATTN_c + tid];
        }
        shw[tid] = (s0 + s1) + (s2 + s3);
    }
    __syncthreads();
    const int warp = tid >> 5, lane = tid & 31;
    for (int n = warp; n < NFEAT; n += 16) {
        const float* uf = Uf + ((size_t)b * NFEAT + n) * ATTN_c;
        float s = 0.f;
#pragma unroll 4
        for (int k = lane; k < ATTN_c; k += 32)
            s += tanh_fast(uf[k] + shw[k]) * swa[k];
#pragma unroll
        for (int o = 16; o; o >>= 1) s += __shfl_xor_sync(0xffffffffu, s, o);
        if (lane == 0) sa[n] = s;
    }
    __syncthreads();
    float v = (tid < NFEAT) ? sa[tid] : -INFINITY;
    red[tid] = v; __syncthreads();
    for (int o = 256; o; o >>= 1) {
        if (tid < o) red[tid] = fmaxf(red[tid], red[tid + o]);
        __syncthreads();
    }
    const float mx = red[0]; __syncthreads();
    const float e = (tid < NFEAT) ? __expf(v - mx) : 0.f;
    red[tid] = e; __syncthreads();
    for (int o = 256; o; o >>= 1) {
        if (tid < o) red[tid] += red[tid + o];
        __syncthreads();
    }
    const float inv = 1.f / red[0];
    if (tid < NFEAT) {
        const float a = e * inv;
        alpha[b * NFEAT + tid] = a;
        if (outAttn) outAttn[(size_t)b * TSTEPS * NFEAT + tid] = a;
    }
}

// ======== context = alpha @ features -> XSp head (split) ====================
__global__ __launch_bounds__(256)
void context_kernel(const float* __restrict__ feat,
                    const float* __restrict__ alpha,
                    uint32_t* __restrict__ XSp)
{
    const int b = blockIdx.x, y = blockIdx.y, tid = threadIdx.x;
    __shared__ float sa[NFEAT];
    for (int n = tid; n < NFEAT; n += 256) sa[n] = alpha[b * NFEAT + n];
    __syncthreads();
    const int j = y * 512 + tid * 2;
    float s0 = 0.f, s1 = 0.f;
    const float* fb = feat + (size_t)b * NFEAT * ENC_Hc + j;
#pragma unroll 4
    for (int n = 0; n < NFEAT; n++) {
        const float al = sa[n];
        const float2 fv = *(const float2*)(fb + (size_t)n * ENC_Hc);
        s0 += al * fv.x; s1 += al * fv.y;
    }
    store_split(XSp, b, XDIM, j, s0, s1);
}

// =============== LSTM pointwise: h, c, XSp tail, HallSp[t][b] ===============
__global__ void lstm_kernel(const float* __restrict__ P,
                            const float* __restrict__ GembT,
                            const float* __restrict__ bhh,
                            float* __restrict__ h,
                            float* __restrict__ c,
                            uint32_t* __restrict__ XSp,
                            uint32_t* __restrict__ HallSp, int t)
{
    const int b = blockIdx.x;
    const int j = blockIdx.y * 256 + threadIdx.x;
    const size_t ps = (size_t)B_ * GDIM;
    float g[4];
#pragma unroll
    for (int q = 0; q < 4; q++) {
        const int col = q * DEC_Hc + j;
        float s = GembT[(size_t)b * GDIM + col] + bhh[col];
#pragma unroll
        for (int z = 0; z < SPLITK_GATES; z++)
            s += P[z * ps + (size_t)b * GDIM + col];
        g[q] = s;
    }
    const float ig = 1.f / (1.f + __expf(-g[0]));
    const float fg = 1.f / (1.f + __expf(-g[1]));
    const float gg = tanhf(g[2]);
    const float og = 1.f / (1.f + __expf(-g[3]));
    const float cn = fg * c[b * DEC_Hc + j] + ig * gg;
    const float hn = og * tanhf(cn);
    c[b * DEC_Hc + j] = cn;
    h[b * DEC_Hc + j] = hn;
    const float hn1 = __shfl_down_sync(0xffffffffu, hn, 1);
    if ((j & 1) == 0) {
        store_split(HallSp, (size_t)t * B_ + b, DEC_Hc, j, hn, hn1);
        store_split(XSp, b, XDIM, ENC_Hc + j, hn, hn1);
    }
}

// ---------------------------------------------------------------------------
extern "C" void kernel_launch(void* const* d_in, const int* in_sizes, int n_in,
                              void* d_out, int out_size)
{
    const float* features = (const float*)d_in[0];
    const int*   captions = (const int*)d_in[1];
    const float* emb_tab  = (const float*)d_in[2];
    const float* W_u  = (const float*)d_in[3];
    const float* b_u  = (const float*)d_in[4];
    const float* W_w  = (const float*)d_in[5];
    const float* b_w  = (const float*)d_in[6];
    const float* W_a  = (const float*)d_in[7];
    const float* W_ih = (const float*)d_in[9];
    const float* b_ih = (const float*)d_in[10];
    const float* W_hh = (const float*)d_in[11];
    const float* b_hh = (const float*)d_in[12];
    const float* W_fc = (const float*)d_in[13];
    const float* b_fc = (const float*)d_in[14];
    const float* W_h0 = (const float*)d_in[15];
    const float* b_h0 = (const float*)d_in[16];
    const float* W_c0 = (const float*)d_in[17];
    const float* b_c0 = (const float*)d_in[18];

    float* outPred = (float*)d_out;
    const size_t predElems = (size_t)B_ * TSTEPS * VOCAB_c;
    const size_t attnElems = (size_t)B_ * TSTEPS * NFEAT;
    float* outAttn =
        ((size_t)out_size >= predElems + attnElems) ? outPred + predElems : nullptr;

    float *pUf, *pFM, *pH, *pC, *pAl, *pGP, *pGE;
    uint32_t *pFSp, *pESp, *pXSp, *pHSp, *pWuSp, *pWihSp, *pWfcSp, *pWcatSp;
    cudaGetSymbolAddress((void**)&pUf, g_Uf);
    cudaGetSymbolAddress((void**)&pFM, g_featmean);
    cudaGetSymbolAddress((void**)&pH,  g_h);
    cudaGetSymbolAddress((void**)&pC,  g_c);
    cudaGetSymbolAddress((void**)&pAl, g_alpha);
    cudaGetSymbolAddress((void**)&pGP, g_GatesPart);
    cudaGetSymbolAddress((void**)&pGE, g_Gemb);
    cudaGetSymbolAddress((void**)&pFSp, g_featSp);
    cudaGetSymbolAddress((void**)&pESp, g_EmbSp);
    cudaGetSymbolAddress((void**)&pXSp, g_XSp);
    cudaGetSymbolAddress((void**)&pHSp, g_HallSp);
    cudaGetSymbolAddress((void**)&pWuSp,  g_WuSp);
    cudaGetSymbolAddress((void**)&pWihSp, g_WihSp);
    cudaGetSymbolAddress((void**)&pWfcSp, g_WfcSp);
    cudaGetSymbolAddress((void**)&pWcatSp, g_WcatSp);

    const int SM128 = 3 * (128 * 8 + 128 * 8) * 16;   // 98304
    const int SM64  = 3 * (64 * 8 + 128 * 8) * 16;    // 73728
    cudaFuncSetAttribute(tg<128>, cudaFuncAttributeMaxDynamicSharedMemorySize,
                         SM128);
    cudaFuncSetAttribute(tg<64>, cudaFuncAttributeMaxDynamicSharedMemorySize,
                         SM64);
    const dim3 tsb(32, 8);

    // side stream + events for overlapped per-step logits (capture fork/join)
    cudaStream_t side;
    cudaStreamCreateWithFlags(&side, cudaStreamNonBlocking);
    cudaEvent_t evStep[TSTEPS + 1];
    for (int i = 0; i <= TSTEPS; i++)
        cudaEventCreateWithFlags(&evStep[i], cudaEventDisableTiming);

    // ---- prologue ----
    feat_mean_kernel<<<dim3(B_, ENC_Hc / 256), 256>>>(features, pFM);
    row_split<<<(int)(((size_t)B_ * NFEAT * ENC_Hc / 4 + 255) / 256), 256>>>(
        features, pFSp, (size_t)B_ * NFEAT * ENC_Hc);
    ts_split<<<dim3(ATTN_c / 32, ENC_Hc / 64), tsb>>>(W_u, ATTN_c, pWuSp,
                                                      ENC_Hc, 0);
    tg<128><<<dim3(B_ * NFEAT / 128, ATTN_c / 128, 1), 256, SM128>>>(
        pFSp, ENC_Hc, pWuSp, ENC_Hc, b_u, pUf, B_ * NFEAT, ATTN_c, ATTN_c,
        ENC_Hc);
    sgemm128<<<dim3(1, DEC_Hc / 128), 256>>>(pFM, ENC_Hc, W_h0, DEC_Hc,
                                             ENC_Hc, b_h0, pH, B_);
    sgemm128<<<dim3(1, DEC_Hc / 128), 256>>>(pFM, ENC_Hc, W_c0, DEC_Hc,
                                             ENC_Hc, b_c0, pC, B_);
    h0split_kernel<<<B_, 512>>>(pH, pXSp);
    ts_split<<<dim3(GDIM / 32, EMB_c / 64), tsb>>>(W_ih, GDIM, pWihSp,
                                                   EMB_c, 0);
    ts_split<<<dim3(VOCAB_c / 32, DEC_Hc / 64), tsb>>>(W_fc, VOCAB_c, pWfcSp,
                                                       DEC_Hc, 0);
    ts_split<<<dim3(GDIM / 32, ENC_Hc / 64), tsb>>>(W_ih + (size_t)EMB_c * GDIM,
                                                    GDIM, pWcatSp, XDIM, 0);
    ts_split<<<dim3(GDIM / 32, DEC_Hc / 64), tsb>>>(W_hh, GDIM, pWcatSp,
                                                    XDIM, ENC_Hc);
    emb_gather_kernel<<<TSTEPS * B_, 128>>>(captions, emb_tab, pESp);
    tg<128><<<dim3((TSTEPS * B_ + 127) / 128, GDIM / 128, 1), 256, SM128>>>(
        pESp, EMB_c, pWihSp, EMB_c, b_ih, pGE, TSTEPS * B_, GDIM, GDIM,
        EMB_c);

    // fork: side stream joins capture after prologue (WfcSp ready)
    cudaEventRecord(evStep[TSTEPS], 0);
    cudaStreamWaitEvent(side, evStep[TSTEPS], 0);

    // ---- recurrence; logits for step t overlapped on side stream ----
    for (int t = 0; t < TSTEPS; t++) {
        attn_kernel<<<B_, 512>>>(pUf, pH, W_w, b_w, W_a, pAl,
                                 outAttn ? outAttn + (size_t)t * NFEAT
                                         : nullptr);
        context_kernel<<<dim3(B_, ENC_Hc / 512), 256>>>(features, pAl, pXSp);
        tg<64><<<dim3(1, GDIM / 128, SPLITK_GATES), 256, SM64>>>(
            pXSp, XDIM, pWcatSp, XDIM, nullptr, pGP,
            B_, GDIM, GDIM, XDIM / SPLITK_GATES);
        lstm_kernel<<<dim3(B_, 4), 256>>>(pGP, pGE + (size_t)t * B_ * GDIM,
                                          b_hh, pH, pC, pXSp, pHSp, t);
        cudaEventRecord(evStep[t], 0);
        cudaStreamWaitEvent(side, evStep[t], 0);
        // logits rows for step t: [64,1024] @ WfcSp -> preds[:, t, :]
        tg<64><<<dim3(1, VOCAB_c / 128, 1), 256, SM64, side>>>(
            pHSp + (size_t)t * B_ * DEC_Hc, DEC_Hc, pWfcSp, DEC_Hc, b_fc,
            outPred + (size_t)t * VOCAB_c, B_, VOCAB_c, TSTEPS * VOCAB_c,
            DEC_Hc);
    }

    // join side stream back into the primary stream
    cudaEvent_t evJoin;
    cudaEventCreateWithFlags(&evJoin, cudaEventDisableTiming);
    cudaEventRecord(evJoin, side);
    cudaStreamWaitEvent(0, evJoin, 0);
}